// round 2
// baseline (speedup 1.0000x reference)
#include <cuda_runtime.h>

#define B_    8
#define N_    1024
#define DIM_  256
#define H_    4
#define DH_   32
#define HID_  128
#define QKV_  384
#define INDC_ 5
#define SCALE_ 0.17677669529663687f
#define EPS_  1e-5f

// ---------------- scratch (static device arrays; no allocation) ----------------
__device__ float g_qkv[B_*QKV_*N_];   // q rows softmaxed in place, k rows softmaxed in place
__device__ float g_vT [B_*N_*HID_];   // v transposed: [b][j][hd]
__device__ float g_KV [B_*H_*DH_*DH_];// KV[b][h][e][d]
__device__ float g_o2 [B_*HID_*N_];   // attention output, hd-major: [b][hd][i]
__device__ float g_y  [B_*DIM_*N_];   // pre-LN projection output

// =================================================================
// Kernel A: qkv[b] = W_qkv (384x256) @ x[b] (256x1024). 64x64 tile.
// =================================================================
__global__ void __launch_bounds__(256) kA(const float* __restrict__ W,
                                          const float* __restrict__ x) {
    int it = blockIdx.x, ot = blockIdx.y, b = blockIdx.z;
    int o0 = ot * 64, i0 = it * 64;
    __shared__ float As[16][65];
    __shared__ float Bs[16][64];
    int t = threadIdx.x;
    int tx = t & 15, ty = t >> 4;
    const float* xb = x + (long)b * DIM_ * N_;

    int m  = t >> 2, kq  = (t & 3) * 4;
    int kk = t >> 4, seg = t & 15;

    float4 pa = *(const float4*)(W  + (o0 + m) * DIM_ + kq);
    float4 pb = *(const float4*)(xb + kk * N_ + i0 + seg * 4);

    float acc[4][4] = {};
    for (int k0 = 0; k0 < DIM_; k0 += 16) {
        if (k0) __syncthreads();
        As[kq+0][m] = pa.x; As[kq+1][m] = pa.y; As[kq+2][m] = pa.z; As[kq+3][m] = pa.w;
        *(float4*)&Bs[kk][seg*4] = pb;
        if (k0 + 16 < DIM_) {
            pa = *(const float4*)(W  + (o0 + m) * DIM_ + k0 + 16 + kq);
            pb = *(const float4*)(xb + (k0 + 16 + kk) * N_ + i0 + seg * 4);
        }
        __syncthreads();
        #pragma unroll
        for (int k = 0; k < 16; k++) {
            float a0 = As[k][ty*4+0], a1 = As[k][ty*4+1];
            float a2 = As[k][ty*4+2], a3 = As[k][ty*4+3];
            float4 b4 = *(float4*)&Bs[k][tx*4];
            acc[0][0]+=a0*b4.x; acc[0][1]+=a0*b4.y; acc[0][2]+=a0*b4.z; acc[0][3]+=a0*b4.w;
            acc[1][0]+=a1*b4.x; acc[1][1]+=a1*b4.y; acc[1][2]+=a1*b4.z; acc[1][3]+=a1*b4.w;
            acc[2][0]+=a2*b4.x; acc[2][1]+=a2*b4.y; acc[2][2]+=a2*b4.z; acc[2][3]+=a2*b4.w;
            acc[3][0]+=a3*b4.x; acc[3][1]+=a3*b4.y; acc[3][2]+=a3*b4.z; acc[3][3]+=a3*b4.w;
        }
    }
    #pragma unroll
    for (int a = 0; a < 4; a++)
        *(float4*)(g_qkv + ((long)b*QKV_ + o0 + ty*4 + a) * N_ + i0 + tx*4) =
            make_float4(acc[a][0], acc[a][1], acc[a][2], acc[a][3]);
}

// =================================================================
// Kernel Q: softmax over d (32) of q, * SCALE, in place.
// grid (8 i-tiles of 128, 4 h, 8 b), 128 threads
// =================================================================
__global__ void __launch_bounds__(128) kQ() {
    int it = blockIdx.x, h = blockIdx.y, b = blockIdx.z;
    int i0 = it * 128, t = threadIdx.x;
    __shared__ float s[32][129];
    #pragma unroll
    for (int r = 0; r < 8; r++) {
        int idx = t + r * 128;
        int d = idx >> 5, c4 = idx & 31;
        float4 v = *(const float4*)(g_qkv + ((long)b*QKV_ + h*DH_ + d) * N_ + i0 + c4*4);
        s[d][c4*4+0] = v.x; s[d][c4*4+1] = v.y; s[d][c4*4+2] = v.z; s[d][c4*4+3] = v.w;
    }
    __syncthreads();
    float m = -1e30f;
    #pragma unroll
    for (int d = 0; d < 32; d++) m = fmaxf(m, s[d][t]);
    float sum = 0.f;
    #pragma unroll
    for (int d = 0; d < 32; d++) { float e = __expf(s[d][t] - m); s[d][t] = e; sum += e; }
    float inv = SCALE_ / sum;
    #pragma unroll
    for (int d = 0; d < 32; d++)
        g_qkv[((long)b*QKV_ + h*DH_ + d) * N_ + i0 + t] = s[d][t] * inv;
}

// =================================================================
// Kernel K: softmax over n (1024) of each k row, in place.
// grid (128 rows, 8 b), 256 threads
// =================================================================
__global__ void __launch_bounds__(256) kK() {
    int row = blockIdx.x, b = blockIdx.y;
    float* p = g_qkv + ((long)b*QKV_ + HID_ + row) * N_;
    int t = threadIdx.x;
    __shared__ float red[8];
    float4 v = *(const float4*)(p + t*4);
    float m = fmaxf(fmaxf(v.x, v.y), fmaxf(v.z, v.w));
    #pragma unroll
    for (int o = 16; o; o >>= 1) m = fmaxf(m, __shfl_xor_sync(0xffffffffu, m, o));
    if ((t & 31) == 0) red[t >> 5] = m;
    __syncthreads();
    m = red[0];
    #pragma unroll
    for (int w = 1; w < 8; w++) m = fmaxf(m, red[w]);
    float e0 = __expf(v.x - m), e1 = __expf(v.y - m);
    float e2 = __expf(v.z - m), e3 = __expf(v.w - m);
    float s = e0 + e1 + e2 + e3;
    #pragma unroll
    for (int o = 16; o; o >>= 1) s += __shfl_xor_sync(0xffffffffu, s, o);
    __syncthreads();
    if ((t & 31) == 0) red[t >> 5] = s;
    __syncthreads();
    float tot = 0.f;
    #pragma unroll
    for (int w = 0; w < 8; w++) tot += red[w];
    float inv = 1.f / tot;
    *(float4*)(p + t*4) = make_float4(e0*inv, e1*inv, e2*inv, e3*inv);
}

// =================================================================
// Kernel V: transpose v -> vT[b][j][hd]. grid (8 j-tiles of 128, 8 b)
// =================================================================
__global__ void __launch_bounds__(256) kV() {
    int it = blockIdx.x, b = blockIdx.y;
    int i0 = it * 128, t = threadIdx.x;
    __shared__ float s[32][129];
    for (int ch = 0; ch < 4; ch++) {
        int hd0 = ch * 32;
        if (ch) __syncthreads();
        #pragma unroll
        for (int r = 0; r < 4; r++) {
            int idx = t + r * 256;
            int d = idx >> 5, c4 = idx & 31;
            float4 v = *(const float4*)(g_qkv + ((long)b*QKV_ + 2*HID_ + hd0 + d) * N_ + i0 + c4*4);
            s[d][c4*4+0] = v.x; s[d][c4*4+1] = v.y; s[d][c4*4+2] = v.z; s[d][c4*4+3] = v.w;
        }
        __syncthreads();
        #pragma unroll
        for (int r = 0; r < 4; r++) {
            int idx = t + r * 256;
            int ii = idx >> 3, d4 = idx & 7;
            float4 o = make_float4(s[d4*4+0][ii], s[d4*4+1][ii], s[d4*4+2][ii], s[d4*4+3][ii]);
            *(float4*)(g_vT + ((long)b*N_ + i0 + ii) * HID_ + hd0 + d4*4) = o;
        }
    }
}

// =================================================================
// Kernel KV: KV[b][h][e][d] = sum_j k[e][j]*v[d][j]. grid 32 (b*h)
// =================================================================
__global__ void __launch_bounds__(256) kKV() {
    int bh = blockIdx.x; int b = bh >> 2, h = bh & 3;
    __shared__ float ksm[32][33], vsm[32][33];
    int t = threadIdx.x;
    int e = t >> 3, d0 = (t & 7) * 4;
    float acc[4] = {};
    const float* kbase = g_qkv + ((long)b*QKV_ + HID_ + h*DH_) * N_;
    for (int j0 = 0; j0 < N_; j0 += 32) {
        if (j0) __syncthreads();
        {
            int ee = t >> 3, j4 = t & 7;
            float4 kv = *(const float4*)(kbase + ee * N_ + j0 + j4*4);
            ksm[ee][j4*4+0] = kv.x; ksm[ee][j4*4+1] = kv.y;
            ksm[ee][j4*4+2] = kv.z; ksm[ee][j4*4+3] = kv.w;
            float4 vv = *(const float4*)(g_vT + ((long)b*N_ + j0 + ee) * HID_ + h*DH_ + j4*4);
            vsm[ee][j4*4+0] = vv.x; vsm[ee][j4*4+1] = vv.y;
            vsm[ee][j4*4+2] = vv.z; vsm[ee][j4*4+3] = vv.w;
        }
        __syncthreads();
        #pragma unroll 8
        for (int jj = 0; jj < 32; jj++) {
            float kk = ksm[e][jj];
            acc[0] += kk * vsm[jj][d0+0];
            acc[1] += kk * vsm[jj][d0+1];
            acc[2] += kk * vsm[jj][d0+2];
            acc[3] += kk * vsm[jj][d0+3];
        }
    }
    *(float4*)(g_KV + ((long)bh*DH_ + e) * DH_ + d0) = make_float4(acc[0], acc[1], acc[2], acc[3]);
}

// =================================================================
// Kernel Lin: o2[b][h*32+d][i] = sum_e q[b,h,e,i] * KV[b,h,e,d]
// grid (8 i-tiles of 128, 4 h, 8 b), 128 threads
// =================================================================
__global__ void __launch_bounds__(128) kLin() {
    int it = blockIdx.x, h = blockIdx.y, b = blockIdx.z;
    int i0 = it * 128, t = threadIdx.x;
    __shared__ float q_s[32][129];
    __shared__ float kv_s[32][33];
    for (int e = 0; e < 32; e++)
        q_s[e][t] = g_qkv[((long)b*QKV_ + h*DH_ + e) * N_ + i0 + t];
    #pragma unroll
    for (int r = 0; r < 8; r++) {
        int idx = t + r * 128;
        int e = idx >> 5, d = idx & 31;
        kv_s[e][d] = g_KV[(((long)(b*H_ + h))*DH_ + e) * DH_ + d];
    }
    __syncthreads();
    float acc[32] = {};
    #pragma unroll 4
    for (int e = 0; e < 32; e++) {
        float qv = q_s[e][t];
        #pragma unroll
        for (int d = 0; d < 32; d++) acc[d] += qv * kv_s[e][d];
    }
    #pragma unroll
    for (int d = 0; d < 32; d++)
        g_o2[((long)b*HID_ + h*DH_ + d) * N_ + i0 + t] = acc[d];
}

// =================================================================
// Kernel C (heavy): o2[b][hd][i] += sum_j qk_h[i][j] * v[hd][j]
//   qk_h[i][j] = sum_c W_ind[h][c]*ind[b][c][i][j]   (fused)
// grid (32 i-tiles of 32, 8 b), 512 threads, j-tiles of 32
// =================================================================
__global__ void __launch_bounds__(512) kC(const float* __restrict__ ind,
                                          const float* __restrict__ Wind) {
    int it = blockIdx.x, b = blockIdx.y;
    int i0 = it * 32, t = threadIdx.x;
    __shared__ float qk_s[4][32][33];   // [h][i][j]
    __shared__ float v_s[32][128];      // [j][hd]

    float w[4][5];
    #pragma unroll
    for (int h2 = 0; h2 < 4; h2++)
        #pragma unroll
        for (int c = 0; c < 5; c++) w[h2][c] = Wind[h2*INDC_ + c];

    int h = t >> 7, u = t & 127;
    int ii0 = (u >> 3) * 2, d0 = (u & 7) * 4;   // 2 i x 4 d per thread
    int l_ii = (t >> 4) & 31, l_j2 = t & 15;    // qk staging (t<512 covers 32x16 twice; use t>>4 low 5 bits)

    float acc[2][4] = {};

    for (int jt = 0; jt < 32; jt++) {
        int j0 = jt * 32;
        if (jt) __syncthreads();
        // stage v tile [32 j][128 hd]
        #pragma unroll
        for (int r = 0; r < 2; r++) {
            int idx = t + r * 512;
            int jj = idx >> 5, c4 = idx & 31;
            *(float4*)&v_s[jj][c4*4] =
                *(const float4*)(g_vT + ((long)b*N_ + j0 + jj) * HID_ + c4*4);
        }
        // stage qk tile: only first 512 mappings needed; each thread does 2 j-floats
        if (t < 512) {
            float2 iv[5];
            #pragma unroll
            for (int c = 0; c < 5; c++)
                iv[c] = *(const float2*)(ind +
                    (((long)(b*INDC_ + c) << 10) + i0 + l_ii) * N_ + j0 + l_j2*2);
            #pragma unroll
            for (int h2 = 0; h2 < 4; h2++) {
                float a0 = 0.f, a1 = 0.f;
                #pragma unroll
                for (int c = 0; c < 5; c++) { a0 += w[h2][c]*iv[c].x; a1 += w[h2][c]*iv[c].y; }
                qk_s[h2][l_ii][l_j2*2+0] = a0;
                qk_s[h2][l_ii][l_j2*2+1] = a1;
            }
        }
        __syncthreads();
        #pragma unroll 8
        for (int jj = 0; jj < 32; jj++) {
            float q0 = qk_s[h][ii0+0][jj];
            float q1 = qk_s[h][ii0+1][jj];
            float4 v4 = *(float4*)&v_s[jj][h*32 + d0];
            acc[0][0]+=q0*v4.x; acc[0][1]+=q0*v4.y; acc[0][2]+=q0*v4.z; acc[0][3]+=q0*v4.w;
            acc[1][0]+=q1*v4.x; acc[1][1]+=q1*v4.y; acc[1][2]+=q1*v4.z; acc[1][3]+=q1*v4.w;
        }
    }
    // stage outputs into smem (reuse qk_s) then coalesced RMW into g_o2
    __syncthreads();
    float* out_s = &qk_s[0][0][0];   // stride 129 layout [ii][c], 31*129+127 < 4224
    #pragma unroll
    for (int a = 0; a < 2; a++)
        #pragma unroll
        for (int dd = 0; dd < 4; dd++)
            out_s[(ii0+a)*129 + h*32 + d0 + dd] = acc[a][dd];
    __syncthreads();
    #pragma unroll
    for (int r = 0; r < 8; r++) {
        int idx = t + r * 512;
        int c = idx >> 5, ii = idx & 31;
        long p = ((long)b*HID_ + c) * N_ + i0 + ii;
        g_o2[p] += out_s[ii*129 + c];
    }
}

// =================================================================
// Kernel D: y[b] = W_out (256x128) @ o2[b] (128x1024) + b_out
// =================================================================
__global__ void __launch_bounds__(256) kD(const float* __restrict__ W,
                                          const float* __restrict__ bias) {
    int it = blockIdx.x, ot = blockIdx.y, b = blockIdx.z;
    int o0 = ot * 64, i0 = it * 64;
    __shared__ float As[16][65];
    __shared__ float Bs[16][64];
    int t = threadIdx.x;
    int tx = t & 15, ty = t >> 4;
    const float* xb = g_o2 + (long)b * HID_ * N_;

    int m  = t >> 2, kq  = (t & 3) * 4;
    int kk = t >> 4, seg = t & 15;

    float4 pa = *(const float4*)(W  + (o0 + m) * HID_ + kq);
    float4 pb = *(const float4*)(xb + kk * N_ + i0 + seg * 4);

    float acc[4][4] = {};
    for (int k0 = 0; k0 < HID_; k0 += 16) {
        if (k0) __syncthreads();
        As[kq+0][m] = pa.x; As[kq+1][m] = pa.y; As[kq+2][m] = pa.z; As[kq+3][m] = pa.w;
        *(float4*)&Bs[kk][seg*4] = pb;
        if (k0 + 16 < HID_) {
            pa = *(const float4*)(W  + (o0 + m) * HID_ + k0 + 16 + kq);
            pb = *(const float4*)(xb + (k0 + 16 + kk) * N_ + i0 + seg * 4);
        }
        __syncthreads();
        #pragma unroll
        for (int k = 0; k < 16; k++) {
            float a0 = As[k][ty*4+0], a1 = As[k][ty*4+1];
            float a2 = As[k][ty*4+2], a3 = As[k][ty*4+3];
            float4 b4 = *(float4*)&Bs[k][tx*4];
            acc[0][0]+=a0*b4.x; acc[0][1]+=a0*b4.y; acc[0][2]+=a0*b4.z; acc[0][3]+=a0*b4.w;
            acc[1][0]+=a1*b4.x; acc[1][1]+=a1*b4.y; acc[1][2]+=a1*b4.z; acc[1][3]+=a1*b4.w;
            acc[2][0]+=a2*b4.x; acc[2][1]+=a2*b4.y; acc[2][2]+=a2*b4.z; acc[2][3]+=a2*b4.w;
            acc[3][0]+=a3*b4.x; acc[3][1]+=a3*b4.y; acc[3][2]+=a3*b4.z; acc[3][3]+=a3*b4.w;
        }
    }
    #pragma unroll
    for (int a = 0; a < 4; a++) {
        float bo = bias[o0 + ty*4 + a];
        *(float4*)(g_y + ((long)b*DIM_ + o0 + ty*4 + a) * N_ + i0 + tx*4) =
            make_float4(acc[a][0]+bo, acc[a][1]+bo, acc[a][2]+bo, acc[a][3]+bo);
    }
}

// =================================================================
// Kernel LN: LayerNorm over channel dim (256) per (b, i)
// grid (8 i-tiles of 128, 8 b), 128 threads
// =================================================================
__global__ void __launch_bounds__(128) kLN(const float* __restrict__ g,
                                           float* __restrict__ out) {
    int it = blockIdx.x, b = blockIdx.y;
    int i = it * 128 + threadIdx.x;
    __shared__ float g_s[DIM_];
    for (int o = threadIdx.x; o < DIM_; o += 128) g_s[o] = g[o];
    __syncthreads();
    const float* yb = g_y + (long)b * DIM_ * N_ + i;
    float sum = 0.f, sq = 0.f;
    for (int o = 0; o < DIM_; o++) {
        float v = yb[(long)o * N_];
        sum += v; sq += v * v;
    }
    float mean = sum * (1.f / DIM_);
    float var  = sq * (1.f / DIM_) - mean * mean;
    float r = rsqrtf(var + EPS_);
    float* ob = out + (long)b * DIM_ * N_ + i;
    for (int o = 0; o < DIM_; o++) {
        float v = yb[(long)o * N_];
        ob[(long)o * N_] = (v - mean) * r * g_s[o];
    }
}

// =================================================================
extern "C" void kernel_launch(void* const* d_in, const int* in_sizes, int n_in,
                              void* d_out, int out_size) {
    const float* x     = (const float*)d_in[0];
    const float* ind   = (const float*)d_in[1];
    const float* Wqkv  = (const float*)d_in[2];
    const float* Wind  = (const float*)d_in[3];
    const float* Wout  = (const float*)d_in[4];
    const float* bout  = (const float*)d_in[5];
    const float* gam   = (const float*)d_in[6];
    float* out = (float*)d_out;

    kA  <<<dim3(16, 6, B_), 256>>>(Wqkv, x);
    kQ  <<<dim3(8, H_, B_), 128>>>();
    kK  <<<dim3(HID_, B_), 256>>>();
    kV  <<<dim3(8, B_), 256>>>();
    kKV <<<dim3(B_*H_), 256>>>();
    kLin<<<dim3(8, H_, B_), 128>>>();
    kC  <<<dim3(32, B_), 512>>>(ind, Wind);
    kD  <<<dim3(16, 4, B_), 256>>>(Wout, bout);
    kLN <<<dim3(8, B_), 128>>>(gam, out);
}

// round 3
// speedup vs baseline: 1.2063x; 1.2063x over previous
#include <cuda_runtime.h>

#define B_    8
#define N_    1024
#define DIM_  256
#define H_    4
#define DH_   32
#define HID_  128
#define QKV_  384
#define INDC_ 5
#define SCALE_ 0.17677669529663687f
#define EPS_  1e-5f

// ---------------- scratch (static device arrays; no allocation) ----------------
__device__ float g_qkv[B_*QKV_*N_];   // q rows softmaxed in place, k rows softmaxed in place
__device__ float g_vT [B_*N_*HID_];   // v transposed: [b][j][hd]
__device__ float g_KV [B_*H_*DH_*DH_];// KV[b][h][e][d]
__device__ float g_o2 [B_*HID_*N_];   // attention output, hd-major: [b][hd][i]
__device__ float g_y  [B_*DIM_*N_];   // pre-LN projection output

__device__ __forceinline__ unsigned tf32u(float f) {
    unsigned u; asm("cvt.rna.tf32.f32 %0, %1;" : "=r"(u) : "f"(f)); return u;
}

__device__ __forceinline__ void mma8(float* c,
                                     unsigned a0, unsigned a1, unsigned a2, unsigned a3,
                                     unsigned b0, unsigned b1) {
    asm volatile("mma.sync.aligned.m16n8k8.row.col.f32.tf32.tf32.f32 "
                 "{%0,%1,%2,%3}, {%4,%5,%6,%7}, {%8,%9}, {%0,%1,%2,%3};\n"
                 : "+f"(c[0]), "+f"(c[1]), "+f"(c[2]), "+f"(c[3])
                 : "r"(a0), "r"(a1), "r"(a2), "r"(a3), "r"(b0), "r"(b1));
}

// =================================================================
// Kernel A: qkv[b] = W_qkv (384x256) @ x[b] (256x1024). 64x64 tile.
// =================================================================
__global__ void __launch_bounds__(256) kA(const float* __restrict__ W,
                                          const float* __restrict__ x) {
    int it = blockIdx.x, ot = blockIdx.y, b = blockIdx.z;
    int o0 = ot * 64, i0 = it * 64;
    __shared__ float As[16][65];
    __shared__ float Bs[16][64];
    int t = threadIdx.x;
    int tx = t & 15, ty = t >> 4;
    const float* xb = x + (long)b * DIM_ * N_;

    int m  = t >> 2, kq  = (t & 3) * 4;
    int kk = t >> 4, seg = t & 15;

    float4 pa = *(const float4*)(W  + (o0 + m) * DIM_ + kq);
    float4 pb = *(const float4*)(xb + kk * N_ + i0 + seg * 4);

    float acc[4][4] = {};
    for (int k0 = 0; k0 < DIM_; k0 += 16) {
        if (k0) __syncthreads();
        As[kq+0][m] = pa.x; As[kq+1][m] = pa.y; As[kq+2][m] = pa.z; As[kq+3][m] = pa.w;
        *(float4*)&Bs[kk][seg*4] = pb;
        if (k0 + 16 < DIM_) {
            pa = *(const float4*)(W  + (o0 + m) * DIM_ + k0 + 16 + kq);
            pb = *(const float4*)(xb + (k0 + 16 + kk) * N_ + i0 + seg * 4);
        }
        __syncthreads();
        #pragma unroll
        for (int k = 0; k < 16; k++) {
            float a0 = As[k][ty*4+0], a1 = As[k][ty*4+1];
            float a2 = As[k][ty*4+2], a3 = As[k][ty*4+3];
            float4 b4 = *(float4*)&Bs[k][tx*4];
            acc[0][0]+=a0*b4.x; acc[0][1]+=a0*b4.y; acc[0][2]+=a0*b4.z; acc[0][3]+=a0*b4.w;
            acc[1][0]+=a1*b4.x; acc[1][1]+=a1*b4.y; acc[1][2]+=a1*b4.z; acc[1][3]+=a1*b4.w;
            acc[2][0]+=a2*b4.x; acc[2][1]+=a2*b4.y; acc[2][2]+=a2*b4.z; acc[2][3]+=a2*b4.w;
            acc[3][0]+=a3*b4.x; acc[3][1]+=a3*b4.y; acc[3][2]+=a3*b4.z; acc[3][3]+=a3*b4.w;
        }
    }
    #pragma unroll
    for (int a = 0; a < 4; a++)
        *(float4*)(g_qkv + ((long)b*QKV_ + o0 + ty*4 + a) * N_ + i0 + tx*4) =
            make_float4(acc[a][0], acc[a][1], acc[a][2], acc[a][3]);
}

// =================================================================
// Kernel Q: softmax over d (32) of q, * SCALE, in place.
// =================================================================
__global__ void __launch_bounds__(128) kQ() {
    int it = blockIdx.x, h = blockIdx.y, b = blockIdx.z;
    int i0 = it * 128, t = threadIdx.x;
    __shared__ float s[32][129];
    #pragma unroll
    for (int r = 0; r < 8; r++) {
        int idx = t + r * 128;
        int d = idx >> 5, c4 = idx & 31;
        float4 v = *(const float4*)(g_qkv + ((long)b*QKV_ + h*DH_ + d) * N_ + i0 + c4*4);
        s[d][c4*4+0] = v.x; s[d][c4*4+1] = v.y; s[d][c4*4+2] = v.z; s[d][c4*4+3] = v.w;
    }
    __syncthreads();
    float m = -1e30f;
    #pragma unroll
    for (int d = 0; d < 32; d++) m = fmaxf(m, s[d][t]);
    float sum = 0.f;
    #pragma unroll
    for (int d = 0; d < 32; d++) { float e = __expf(s[d][t] - m); s[d][t] = e; sum += e; }
    float inv = SCALE_ / sum;
    #pragma unroll
    for (int d = 0; d < 32; d++)
        g_qkv[((long)b*QKV_ + h*DH_ + d) * N_ + i0 + t] = s[d][t] * inv;
}

// =================================================================
// Kernel K: softmax over n (1024) of each k row, in place.
// =================================================================
__global__ void __launch_bounds__(256) kK() {
    int row = blockIdx.x, b = blockIdx.y;
    float* p = g_qkv + ((long)b*QKV_ + HID_ + row) * N_;
    int t = threadIdx.x;
    __shared__ float red[8];
    float4 v = *(const float4*)(p + t*4);
    float m = fmaxf(fmaxf(v.x, v.y), fmaxf(v.z, v.w));
    #pragma unroll
    for (int o = 16; o; o >>= 1) m = fmaxf(m, __shfl_xor_sync(0xffffffffu, m, o));
    if ((t & 31) == 0) red[t >> 5] = m;
    __syncthreads();
    m = red[0];
    #pragma unroll
    for (int w = 1; w < 8; w++) m = fmaxf(m, red[w]);
    float e0 = __expf(v.x - m), e1 = __expf(v.y - m);
    float e2 = __expf(v.z - m), e3 = __expf(v.w - m);
    float s = e0 + e1 + e2 + e3;
    #pragma unroll
    for (int o = 16; o; o >>= 1) s += __shfl_xor_sync(0xffffffffu, s, o);
    __syncthreads();
    if ((t & 31) == 0) red[t >> 5] = s;
    __syncthreads();
    float tot = 0.f;
    #pragma unroll
    for (int w = 0; w < 8; w++) tot += red[w];
    float inv = 1.f / tot;
    *(float4*)(p + t*4) = make_float4(e0*inv, e1*inv, e2*inv, e3*inv);
}

// =================================================================
// Kernel V: transpose v -> vT[b][j][hd].
// =================================================================
__global__ void __launch_bounds__(256) kV() {
    int it = blockIdx.x, b = blockIdx.y;
    int i0 = it * 128, t = threadIdx.x;
    __shared__ float s[32][129];
    for (int ch = 0; ch < 4; ch++) {
        int hd0 = ch * 32;
        if (ch) __syncthreads();
        #pragma unroll
        for (int r = 0; r < 4; r++) {
            int idx = t + r * 256;
            int d = idx >> 5, c4 = idx & 31;
            float4 v = *(const float4*)(g_qkv + ((long)b*QKV_ + 2*HID_ + hd0 + d) * N_ + i0 + c4*4);
            s[d][c4*4+0] = v.x; s[d][c4*4+1] = v.y; s[d][c4*4+2] = v.z; s[d][c4*4+3] = v.w;
        }
        __syncthreads();
        #pragma unroll
        for (int r = 0; r < 4; r++) {
            int idx = t + r * 256;
            int ii = idx >> 3, d4 = idx & 7;
            float4 o = make_float4(s[d4*4+0][ii], s[d4*4+1][ii], s[d4*4+2][ii], s[d4*4+3][ii]);
            *(float4*)(g_vT + ((long)b*N_ + i0 + ii) * HID_ + hd0 + d4*4) = o;
        }
    }
}

// =================================================================
// Kernel KV: KV[b][h][e][d] = sum_j k[e][j]*v[d][j]. grid 32 (b*h)
// =================================================================
__global__ void __launch_bounds__(256) kKV() {
    int bh = blockIdx.x; int b = bh >> 2, h = bh & 3;
    __shared__ float ksm[32][33], vsm[32][33];
    int t = threadIdx.x;
    int e = t >> 3, d0 = (t & 7) * 4;
    float acc[4] = {};
    const float* kbase = g_qkv + ((long)b*QKV_ + HID_ + h*DH_) * N_;
    for (int j0 = 0; j0 < N_; j0 += 32) {
        if (j0) __syncthreads();
        {
            int ee = t >> 3, j4 = t & 7;
            float4 kv = *(const float4*)(kbase + ee * N_ + j0 + j4*4);
            ksm[ee][j4*4+0] = kv.x; ksm[ee][j4*4+1] = kv.y;
            ksm[ee][j4*4+2] = kv.z; ksm[ee][j4*4+3] = kv.w;
            float4 vv = *(const float4*)(g_vT + ((long)b*N_ + j0 + ee) * HID_ + h*DH_ + j4*4);
            vsm[ee][j4*4+0] = vv.x; vsm[ee][j4*4+1] = vv.y;
            vsm[ee][j4*4+2] = vv.z; vsm[ee][j4*4+3] = vv.w;
        }
        __syncthreads();
        #pragma unroll 8
        for (int jj = 0; jj < 32; jj++) {
            float kk = ksm[e][jj];
            acc[0] += kk * vsm[jj][d0+0];
            acc[1] += kk * vsm[jj][d0+1];
            acc[2] += kk * vsm[jj][d0+2];
            acc[3] += kk * vsm[jj][d0+3];
        }
    }
    *(float4*)(g_KV + ((long)bh*DH_ + e) * DH_ + d0) = make_float4(acc[0], acc[1], acc[2], acc[3]);
}

// =================================================================
// Kernel Lin: o2[b][h*32+d][i] = sum_e q[b,h,e,i] * KV[b,h,e,d]
// =================================================================
__global__ void __launch_bounds__(128) kLin() {
    int it = blockIdx.x, h = blockIdx.y, b = blockIdx.z;
    int i0 = it * 128, t = threadIdx.x;
    __shared__ float q_s[32][129];
    __shared__ float kv_s[32][33];
    for (int e = 0; e < 32; e++)
        q_s[e][t] = g_qkv[((long)b*QKV_ + h*DH_ + e) * N_ + i0 + t];
    #pragma unroll
    for (int r = 0; r < 8; r++) {
        int idx = t + r * 128;
        int e = idx >> 5, d = idx & 31;
        kv_s[e][d] = g_KV[(((long)(b*H_ + h))*DH_ + e) * DH_ + d];
    }
    __syncthreads();
    float acc[32] = {};
    #pragma unroll 4
    for (int e = 0; e < 32; e++) {
        float qv = q_s[e][t];
        #pragma unroll
        for (int d = 0; d < 32; d++) acc[d] += qv * kv_s[e][d];
    }
    #pragma unroll
    for (int d = 0; d < 32; d++)
        g_o2[((long)b*HID_ + h*DH_ + d) * N_ + i0 + t] = acc[d];
}

// =================================================================
// Kernel C (tf32 tensor-core): o2[b][hd][i] += sum_j qk_h[i][j]*v[hd][j]
//   qk_h[i][j] = sum_c W_ind[h][c]*ind[b][c][i][j]  (built on the fly)
// grid (16 i-tiles of 64, 8 b), 256 threads (8 warps, 2 per head).
// j staged 16 at a time; mma.sync.m16n8k8.tf32.
// =================================================================
__global__ void __launch_bounds__(256) kC(const float* __restrict__ ind,
                                          const float* __restrict__ Wind) {
    int it = blockIdx.x, b = blockIdx.y;
    int i0 = it * 64, t = threadIdx.x;
    __shared__ unsigned qk_s[4][64][38];   // [h][i][j] tf32, stride 38 (bank-clean)
    __shared__ unsigned v_s[16][136];      // [j][hd]  tf32, stride 136 (bank-clean)

    int warp = t >> 5, lane = t & 31;
    int h  = warp >> 1;           // 2 warps per head
    int n0 = (warp & 1) * 16;     // this warp's 16 cols within the head's 32
    int g  = lane >> 2, tig = lane & 3;

    float w[4][5];
    #pragma unroll
    for (int hh = 0; hh < 4; hh++)
        #pragma unroll
        for (int c = 0; c < 5; c++) w[hh][c] = Wind[hh*INDC_ + c];

    int s_ii = t >> 2, s_j4 = (t & 3) * 4;
    const float* indb = ind + ((long)b * INDC_ << 20);

    float acc[4][2][4];
    #pragma unroll
    for (int mt = 0; mt < 4; mt++)
        #pragma unroll
        for (int nt = 0; nt < 2; nt++)
            #pragma unroll
            for (int z = 0; z < 4; z++) acc[mt][nt][z] = 0.f;

    float4 pind[5], pv[2];
    // prologue prefetch (j0 = 0)
    #pragma unroll
    for (int c = 0; c < 5; c++)
        pind[c] = *(const float4*)(indb + ((long)c << 20) + (long)(i0 + s_ii) * N_ + s_j4);
    #pragma unroll
    for (int r = 0; r < 2; r++) {
        int idx = t + r*256, jj = idx >> 5, c4 = idx & 31;
        pv[r] = *(const float4*)(g_vT + ((long)b*N_ + jj) * HID_ + c4*4);
    }

    for (int jt = 0; jt < 64; jt++) {
        if (jt) __syncthreads();
        // commit v tile (tf32)
        #pragma unroll
        for (int r = 0; r < 2; r++) {
            int idx = t + r*256, jj = idx >> 5, c4 = idx & 31;
            v_s[jj][c4*4+0] = tf32u(pv[r].x);
            v_s[jj][c4*4+1] = tf32u(pv[r].y);
            v_s[jj][c4*4+2] = tf32u(pv[r].z);
            v_s[jj][c4*4+3] = tf32u(pv[r].w);
        }
        // build qk tile (5-ch contraction, tf32)
        #pragma unroll
        for (int hh = 0; hh < 4; hh++) {
            float o0 = 0.f, o1 = 0.f, o2v = 0.f, o3 = 0.f;
            #pragma unroll
            for (int c = 0; c < 5; c++) {
                float wc = w[hh][c];
                o0 += wc * pind[c].x; o1 += wc * pind[c].y;
                o2v += wc * pind[c].z; o3 += wc * pind[c].w;
            }
            qk_s[hh][s_ii][s_j4+0] = tf32u(o0);
            qk_s[hh][s_ii][s_j4+1] = tf32u(o1);
            qk_s[hh][s_ii][s_j4+2] = tf32u(o2v);
            qk_s[hh][s_ii][s_j4+3] = tf32u(o3);
        }
        // prefetch next stage
        if (jt + 1 < 64) {
            int j0n = (jt + 1) * 16;
            #pragma unroll
            for (int c = 0; c < 5; c++)
                pind[c] = *(const float4*)(indb + ((long)c << 20) + (long)(i0 + s_ii) * N_ + j0n + s_j4);
            #pragma unroll
            for (int r = 0; r < 2; r++) {
                int idx = t + r*256, jj = idx >> 5, c4 = idx & 31;
                pv[r] = *(const float4*)(g_vT + ((long)b*N_ + j0n + jj) * HID_ + c4*4);
            }
        }
        __syncthreads();
        // MMA: 2 k-steps of 8
        #pragma unroll
        for (int ks = 0; ks < 2; ks++) {
            int k0 = ks * 8;
            unsigned bfr[2][2];
            #pragma unroll
            for (int nt = 0; nt < 2; nt++) {
                int c = h*32 + n0 + nt*8 + g;
                bfr[nt][0] = v_s[k0 + tig][c];
                bfr[nt][1] = v_s[k0 + tig + 4][c];
            }
            #pragma unroll
            for (int mt = 0; mt < 4; mt++) {
                int r = mt*16 + g;
                unsigned a0 = qk_s[h][r    ][k0 + tig];
                unsigned a1 = qk_s[h][r + 8][k0 + tig];
                unsigned a2 = qk_s[h][r    ][k0 + tig + 4];
                unsigned a3 = qk_s[h][r + 8][k0 + tig + 4];
                mma8(acc[mt][0], a0, a1, a2, a3, bfr[0][0], bfr[0][1]);
                mma8(acc[mt][1], a0, a1, a2, a3, bfr[1][0], bfr[1][1]);
            }
        }
    }

    // epilogue: stage C frags to smem (alias qk region), then coalesced += to g_o2
    __syncthreads();
    float* out_s = (float*)&qk_s[0][0][0];   // [i][hd] stride 129: 64*129 floats < region
    #pragma unroll
    for (int mt = 0; mt < 4; mt++) {
        int r = mt*16 + g;
        #pragma unroll
        for (int nt = 0; nt < 2; nt++) {
            int c = h*32 + n0 + nt*8 + tig*2;
            out_s[ r     *129 + c    ] = acc[mt][nt][0];
            out_s[ r     *129 + c + 1] = acc[mt][nt][1];
            out_s[(r + 8)*129 + c    ] = acc[mt][nt][2];
            out_s[(r + 8)*129 + c + 1] = acc[mt][nt][3];
        }
    }
    __syncthreads();
    #pragma unroll
    for (int r2 = 0; r2 < 32; r2++) {
        int idx = t + r2*256, c = idx >> 6, ii = idx & 63;
        long p = ((long)b*HID_ + c) * N_ + i0 + ii;
        g_o2[p] += out_s[ii*129 + c];
    }
}

// =================================================================
// Kernel D: y[b] = W_out (256x128) @ o2[b] (128x1024) + b_out
// =================================================================
__global__ void __launch_bounds__(256) kD(const float* __restrict__ W,
                                          const float* __restrict__ bias) {
    int it = blockIdx.x, ot = blockIdx.y, b = blockIdx.z;
    int o0 = ot * 64, i0 = it * 64;
    __shared__ float As[16][65];
    __shared__ float Bs[16][64];
    int t = threadIdx.x;
    int tx = t & 15, ty = t >> 4;
    const float* xb = g_o2 + (long)b * HID_ * N_;

    int m  = t >> 2, kq  = (t & 3) * 4;
    int kk = t >> 4, seg = t & 15;

    float4 pa = *(const float4*)(W  + (o0 + m) * HID_ + kq);
    float4 pb = *(const float4*)(xb + kk * N_ + i0 + seg * 4);

    float acc[4][4] = {};
    for (int k0 = 0; k0 < HID_; k0 += 16) {
        if (k0) __syncthreads();
        As[kq+0][m] = pa.x; As[kq+1][m] = pa.y; As[kq+2][m] = pa.z; As[kq+3][m] = pa.w;
        *(float4*)&Bs[kk][seg*4] = pb;
        if (k0 + 16 < HID_) {
            pa = *(const float4*)(W  + (o0 + m) * HID_ + k0 + 16 + kq);
            pb = *(const float4*)(xb + (k0 + 16 + kk) * N_ + i0 + seg * 4);
        }
        __syncthreads();
        #pragma unroll
        for (int k = 0; k < 16; k++) {
            float a0 = As[k][ty*4+0], a1 = As[k][ty*4+1];
            float a2 = As[k][ty*4+2], a3 = As[k][ty*4+3];
            float4 b4 = *(float4*)&Bs[k][tx*4];
            acc[0][0]+=a0*b4.x; acc[0][1]+=a0*b4.y; acc[0][2]+=a0*b4.z; acc[0][3]+=a0*b4.w;
            acc[1][0]+=a1*b4.x; acc[1][1]+=a1*b4.y; acc[1][2]+=a1*b4.z; acc[1][3]+=a1*b4.w;
            acc[2][0]+=a2*b4.x; acc[2][1]+=a2*b4.y; acc[2][2]+=a2*b4.z; acc[2][3]+=a2*b4.w;
            acc[3][0]+=a3*b4.x; acc[3][1]+=a3*b4.y; acc[3][2]+=a3*b4.z; acc[3][3]+=a3*b4.w;
        }
    }
    #pragma unroll
    for (int a = 0; a < 4; a++) {
        float bo = bias[o0 + ty*4 + a];
        *(float4*)(g_y + ((long)b*DIM_ + o0 + ty*4 + a) * N_ + i0 + tx*4) =
            make_float4(acc[a][0]+bo, acc[a][1]+bo, acc[a][2]+bo, acc[a][3]+bo);
    }
}

// =================================================================
// Kernel LN: LayerNorm over channel dim (256) per (b, i)
// =================================================================
__global__ void __launch_bounds__(128) kLN(const float* __restrict__ g,
                                           float* __restrict__ out) {
    int it = blockIdx.x, b = blockIdx.y;
    int i = it * 128 + threadIdx.x;
    __shared__ float g_s[DIM_];
    for (int o = threadIdx.x; o < DIM_; o += 128) g_s[o] = g[o];
    __syncthreads();
    const float* yb = g_y + (long)b * DIM_ * N_ + i;
    float sum = 0.f, sq = 0.f;
    for (int o = 0; o < DIM_; o++) {
        float v = yb[(long)o * N_];
        sum += v; sq += v * v;
    }
    float mean = sum * (1.f / DIM_);
    float var  = sq * (1.f / DIM_) - mean * mean;
    float r = rsqrtf(var + EPS_);
    float* ob = out + (long)b * DIM_ * N_ + i;
    for (int o = 0; o < DIM_; o++) {
        float v = yb[(long)o * N_];
        ob[(long)o * N_] = (v - mean) * r * g_s[o];
    }
}

// =================================================================
extern "C" void kernel_launch(void* const* d_in, const int* in_sizes, int n_in,
                              void* d_out, int out_size) {
    const float* x     = (const float*)d_in[0];
    const float* ind   = (const float*)d_in[1];
    const float* Wqkv  = (const float*)d_in[2];
    const float* Wind  = (const float*)d_in[3];
    const float* Wout  = (const float*)d_in[4];
    const float* bout  = (const float*)d_in[5];
    const float* gam   = (const float*)d_in[6];
    float* out = (float*)d_out;

    kA  <<<dim3(16, 6, B_), 256>>>(Wqkv, x);
    kQ  <<<dim3(8, H_, B_), 128>>>();
    kK  <<<dim3(HID_, B_), 256>>>();
    kV  <<<dim3(8, B_), 256>>>();
    kKV <<<dim3(B_*H_), 256>>>();
    kLin<<<dim3(8, H_, B_), 128>>>();
    kC  <<<dim3(16, B_), 256>>>(ind, Wind);
    kD  <<<dim3(16, 4, B_), 256>>>(Wout, bout);
    kLN <<<dim3(8, B_), 128>>>(gam, out);
}

// round 4
// speedup vs baseline: 1.3861x; 1.1491x over previous
#include <cuda_runtime.h>

#define B_    8
#define N_    1024
#define DIM_  256
#define H_    4
#define DH_   32
#define HID_  128
#define QKV_  384
#define INDC_ 5
#define SCALE_ 0.17677669529663687f
#define EPS_  1e-5f

// ---------------- scratch ----------------
__device__ float g_qkv[B_*QKV_*N_];   // q raw, k softmaxed in place, v raw
__device__ float g_KV [B_*H_*DH_*DH_];// KV[b][h][e][d]
__device__ float g_o2 [B_*HID_*N_];   // attention output, hd-major: [b][hd][i]

__device__ __forceinline__ unsigned tf32u(float f) {
    unsigned u; asm("cvt.rna.tf32.f32 %0, %1;" : "=r"(u) : "f"(f)); return u;
}
__device__ __forceinline__ uint2 split_tf32(float v) {
    unsigned hi = tf32u(v);
    float r = v - __uint_as_float(hi);
    return make_uint2(hi, tf32u(r));
}
__device__ __forceinline__ void mma8(float* c,
                                     unsigned a0, unsigned a1, unsigned a2, unsigned a3,
                                     unsigned b0, unsigned b1) {
    asm volatile("mma.sync.aligned.m16n8k8.row.col.f32.tf32.tf32.f32 "
                 "{%0,%1,%2,%3}, {%4,%5,%6,%7}, {%8,%9}, {%0,%1,%2,%3};\n"
                 : "+f"(c[0]), "+f"(c[1]), "+f"(c[2]), "+f"(c[3])
                 : "r"(a0), "r"(a1), "r"(a2), "r"(a3), "r"(b0), "r"(b1));
}

// =================================================================
// Kernel A (tf32 split-MMA): qkv[b] = W_qkv (384x256) @ x[b] (256x1024)
// block tile M=128 x N=64, K chunks of 16. 8 warps (4 m x 2 n), warp m32n32.
// hi/lo split: hi*hi + hi*lo + lo*hi  ==> fp32-accurate.
// =================================================================
__global__ void __launch_bounds__(256) kA(const float* __restrict__ W,
                                          const float* __restrict__ x) {
    int i0 = blockIdx.x * 64, o0 = blockIdx.y * 128, b = blockIdx.z;
    __shared__ unsigned A_s[16][132][2];   // [k][m][hi/lo]
    __shared__ unsigned B_s[16][68][2];    // [k][n][hi/lo]
    int t = threadIdx.x, warp = t >> 5, lane = t & 31;
    int g = lane >> 2, tig = lane & 3;
    int wm = warp >> 1, wn = warp & 1;
    const float* xb = x + (long)b * DIM_ * N_;

    int aq = t & 3, am = t >> 2;     // A stage: m=am(+64r), kquad=aq
    int bq = t & 15, bk = t >> 4;    // B stage: k=bk, nquad=bq

    float4 pa[2], pb;
    #pragma unroll
    for (int r = 0; r < 2; r++)
        pa[r] = *(const float4*)(W + (o0 + am + 64*r) * DIM_ + aq*4);
    pb = *(const float4*)(xb + bk * N_ + i0 + bq*4);

    float acc[2][4][4];
    #pragma unroll
    for (int mt = 0; mt < 2; mt++)
        #pragma unroll
        for (int nt = 0; nt < 4; nt++)
            #pragma unroll
            for (int z = 0; z < 4; z++) acc[mt][nt][z] = 0.f;

    for (int c = 0; c < 16; c++) {
        if (c) __syncthreads();
        // commit chunk
        #pragma unroll
        for (int r = 0; r < 2; r++) {
            const float* pv = (const float*)&pa[r];
            #pragma unroll
            for (int j = 0; j < 4; j++)
                *(uint2*)&A_s[aq*4+j][am + 64*r][0] = split_tf32(pv[j]);
        }
        {
            const float* pv = (const float*)&pb;
            #pragma unroll
            for (int j = 0; j < 4; j++)
                *(uint2*)&B_s[bk][bq*4+j][0] = split_tf32(pv[j]);
        }
        if (c + 1 < 16) {
            int k0n = (c + 1) * 16;
            #pragma unroll
            for (int r = 0; r < 2; r++)
                pa[r] = *(const float4*)(W + (o0 + am + 64*r) * DIM_ + k0n + aq*4);
            pb = *(const float4*)(xb + (k0n + bk) * N_ + i0 + bq*4);
        }
        __syncthreads();
        #pragma unroll
        for (int ks = 0; ks < 2; ks++) {
            int k8 = ks * 8;
            uint2 Bf[4][2];
            #pragma unroll
            for (int nt = 0; nt < 4; nt++) {
                int cn = wn*32 + nt*8 + g;
                Bf[nt][0] = *(uint2*)&B_s[k8 + tig    ][cn][0];
                Bf[nt][1] = *(uint2*)&B_s[k8 + tig + 4][cn][0];
            }
            #pragma unroll
            for (int mt = 0; mt < 2; mt++) {
                int rm = wm*32 + mt*16 + g;
                uint2 A0 = *(uint2*)&A_s[k8 + tig    ][rm    ][0];
                uint2 A1 = *(uint2*)&A_s[k8 + tig    ][rm + 8][0];
                uint2 A2 = *(uint2*)&A_s[k8 + tig + 4][rm    ][0];
                uint2 A3 = *(uint2*)&A_s[k8 + tig + 4][rm + 8][0];
                #pragma unroll
                for (int nt = 0; nt < 4; nt++) {
                    mma8(acc[mt][nt], A0.x, A1.x, A2.x, A3.x, Bf[nt][0].x, Bf[nt][1].x);
                    mma8(acc[mt][nt], A0.x, A1.x, A2.x, A3.x, Bf[nt][0].y, Bf[nt][1].y);
                    mma8(acc[mt][nt], A0.y, A1.y, A2.y, A3.y, Bf[nt][0].x, Bf[nt][1].x);
                }
            }
        }
    }
    // epilogue: direct STG.64 (c-frag rows i-contiguous pairs)
    #pragma unroll
    for (int mt = 0; mt < 2; mt++) {
        int row = o0 + wm*32 + mt*16 + g;
        #pragma unroll
        for (int nt = 0; nt < 4; nt++) {
            int col = i0 + wn*32 + nt*8 + tig*2;
            *(float2*)(g_qkv + ((long)b*QKV_ + row    ) * N_ + col) =
                make_float2(acc[mt][nt][0], acc[mt][nt][1]);
            *(float2*)(g_qkv + ((long)b*QKV_ + row + 8) * N_ + col) =
                make_float2(acc[mt][nt][2], acc[mt][nt][3]);
        }
    }
}

// =================================================================
// Kernel K: softmax over n (1024) of each k row, in place.
// =================================================================
__global__ void __launch_bounds__(256) kK() {
    int row = blockIdx.x, b = blockIdx.y;
    float* p = g_qkv + ((long)b*QKV_ + HID_ + row) * N_;
    int t = threadIdx.x;
    __shared__ float red[8];
    float4 v = *(const float4*)(p + t*4);
    float m = fmaxf(fmaxf(v.x, v.y), fmaxf(v.z, v.w));
    #pragma unroll
    for (int o = 16; o; o >>= 1) m = fmaxf(m, __shfl_xor_sync(0xffffffffu, m, o));
    if ((t & 31) == 0) red[t >> 5] = m;
    __syncthreads();
    m = red[0];
    #pragma unroll
    for (int w = 1; w < 8; w++) m = fmaxf(m, red[w]);
    float e0 = __expf(v.x - m), e1 = __expf(v.y - m);
    float e2 = __expf(v.z - m), e3 = __expf(v.w - m);
    float s = e0 + e1 + e2 + e3;
    #pragma unroll
    for (int o = 16; o; o >>= 1) s += __shfl_xor_sync(0xffffffffu, s, o);
    __syncthreads();
    if ((t & 31) == 0) red[t >> 5] = s;
    __syncthreads();
    float tot = 0.f;
    #pragma unroll
    for (int w = 0; w < 8; w++) tot += red[w];
    float inv = 1.f / tot;
    *(float4*)(p + t*4) = make_float4(e0*inv, e1*inv, e2*inv, e3*inv);
}

// =================================================================
// Kernel KV: KV[b][h][e][d] = sum_j k[e][j]*v[d][j]; k,v read from g_qkv.
// =================================================================
__global__ void __launch_bounds__(256) kKV() {
    int bh = blockIdx.x; int b = bh >> 2, h = bh & 3;
    __shared__ float ksm[32][33], vsm[32][33];   // ksm[e][j], vsm[d][j]
    int t = threadIdx.x;
    int e = t >> 3, d0 = (t & 7) * 4;
    float acc[4] = {};
    const float* kbase = g_qkv + ((long)b*QKV_ + HID_   + h*DH_) * N_;
    const float* vbase = g_qkv + ((long)b*QKV_ + 2*HID_ + h*DH_) * N_;
    for (int j0 = 0; j0 < N_; j0 += 32) {
        if (j0) __syncthreads();
        {
            int ee = t >> 3, j4 = t & 7;
            float4 kv = *(const float4*)(kbase + ee * N_ + j0 + j4*4);
            ksm[ee][j4*4+0] = kv.x; ksm[ee][j4*4+1] = kv.y;
            ksm[ee][j4*4+2] = kv.z; ksm[ee][j4*4+3] = kv.w;
            float4 vv = *(const float4*)(vbase + ee * N_ + j0 + j4*4);
            vsm[ee][j4*4+0] = vv.x; vsm[ee][j4*4+1] = vv.y;
            vsm[ee][j4*4+2] = vv.z; vsm[ee][j4*4+3] = vv.w;
        }
        __syncthreads();
        #pragma unroll 8
        for (int jj = 0; jj < 32; jj++) {
            float kk = ksm[e][jj];
            acc[0] += kk * vsm[d0+0][jj];
            acc[1] += kk * vsm[d0+1][jj];
            acc[2] += kk * vsm[d0+2][jj];
            acc[3] += kk * vsm[d0+3][jj];
        }
    }
    *(float4*)(g_KV + ((long)bh*DH_ + e) * DH_ + d0) = make_float4(acc[0], acc[1], acc[2], acc[3]);
}

// =================================================================
// Kernel Lin (fused q-softmax): o2[b][h*32+d][i] =
//   (SCALE/sum_e) * sum_e exp(q[e][i]-max) * KV[b,h,e,d]
// =================================================================
__global__ void __launch_bounds__(128) kLin() {
    int it = blockIdx.x, h = blockIdx.y, b = blockIdx.z;
    int i0 = it * 128, t = threadIdx.x;
    __shared__ float q_s[32][129];
    __shared__ float kv_s[32][33];
    for (int e = 0; e < 32; e++)
        q_s[e][t] = g_qkv[((long)b*QKV_ + h*DH_ + e) * N_ + i0 + t];
    #pragma unroll
    for (int r = 0; r < 8; r++) {
        int idx = t + r * 128;
        int e = idx >> 5, d = idx & 31;
        kv_s[e][d] = g_KV[(((long)(b*H_ + h))*DH_ + e) * DH_ + d];
    }
    __syncthreads();
    float p[32];
    float m = -1e30f;
    #pragma unroll
    for (int e = 0; e < 32; e++) { p[e] = q_s[e][t]; m = fmaxf(m, p[e]); }
    float s = 0.f;
    #pragma unroll
    for (int e = 0; e < 32; e++) { p[e] = __expf(p[e] - m); s += p[e]; }
    float acc[32] = {};
    #pragma unroll 4
    for (int e = 0; e < 32; e++) {
        float pe = p[e];
        #pragma unroll
        for (int d = 0; d < 32; d++) acc[d] += pe * kv_s[e][d];
    }
    float sc = SCALE_ / s;
    #pragma unroll
    for (int d = 0; d < 32; d++)
        g_o2[((long)b*HID_ + h*DH_ + d) * N_ + i0 + t] = acc[d] * sc;
}

// =================================================================
// Kernel C (tf32 MMA): o2[b][hd][i] += sum_j qk_h[i][j]*v[hd][j]
//   qk from 5-ch indicator contraction; v read directly from g_qkv.
// =================================================================
__global__ void __launch_bounds__(256) kC(const float* __restrict__ ind,
                                          const float* __restrict__ Wind) {
    int it = blockIdx.x, b = blockIdx.y;
    int i0 = it * 64, t = threadIdx.x;
    __shared__ unsigned qk_s[4][64][38];   // [h][i][j] tf32
    __shared__ unsigned v_s[16][136];      // [j][hd]  tf32

    int warp = t >> 5, lane = t & 31;
    int h  = warp >> 1;
    int n0 = (warp & 1) * 16;
    int g  = lane >> 2, tig = lane & 3;

    float w[4][5];
    #pragma unroll
    for (int hh = 0; hh < 4; hh++)
        #pragma unroll
        for (int c = 0; c < 5; c++) w[hh][c] = Wind[hh*INDC_ + c];

    int s_ii = t >> 2, s_j4 = (t & 3) * 4;
    int v_hd = t >> 2, v_jq = t & 3;    // v stage: [hd 0..63(+64)], jquad
    const float* indb = ind + ((long)b * INDC_ << 20);
    const float* vbase = g_qkv + ((long)b*QKV_ + 2*HID_) * N_;

    float acc[4][2][4];
    #pragma unroll
    for (int mt = 0; mt < 4; mt++)
        #pragma unroll
        for (int nt = 0; nt < 2; nt++)
            #pragma unroll
            for (int z = 0; z < 4; z++) acc[mt][nt][z] = 0.f;

    float4 pind[5], pv[2];
    #pragma unroll
    for (int c = 0; c < 5; c++)
        pind[c] = *(const float4*)(indb + ((long)c << 20) + (long)(i0 + s_ii) * N_ + s_j4);
    #pragma unroll
    for (int r = 0; r < 2; r++)
        pv[r] = *(const float4*)(vbase + (long)(v_hd + 64*r) * N_ + v_jq*4);

    for (int jt = 0; jt < 64; jt++) {
        if (jt) __syncthreads();
        // commit v tile (transpose to [j][hd], tf32)
        #pragma unroll
        for (int r = 0; r < 2; r++) {
            const float* pf = (const float*)&pv[r];
            int hd = v_hd + 64*r;
            #pragma unroll
            for (int u = 0; u < 4; u++)
                v_s[v_jq*4+u][hd] = tf32u(pf[u]);
        }
        // build qk tile
        #pragma unroll
        for (int hh = 0; hh < 4; hh++) {
            float o0 = 0.f, o1 = 0.f, o2v = 0.f, o3 = 0.f;
            #pragma unroll
            for (int c = 0; c < 5; c++) {
                float wc = w[hh][c];
                o0 += wc * pind[c].x; o1 += wc * pind[c].y;
                o2v += wc * pind[c].z; o3 += wc * pind[c].w;
            }
            qk_s[hh][s_ii][s_j4+0] = tf32u(o0);
            qk_s[hh][s_ii][s_j4+1] = tf32u(o1);
            qk_s[hh][s_ii][s_j4+2] = tf32u(o2v);
            qk_s[hh][s_ii][s_j4+3] = tf32u(o3);
        }
        if (jt + 1 < 64) {
            int j0n = (jt + 1) * 16;
            #pragma unroll
            for (int c = 0; c < 5; c++)
                pind[c] = *(const float4*)(indb + ((long)c << 20) + (long)(i0 + s_ii) * N_ + j0n + s_j4);
            #pragma unroll
            for (int r = 0; r < 2; r++)
                pv[r] = *(const float4*)(vbase + (long)(v_hd + 64*r) * N_ + j0n + v_jq*4);
        }
        __syncthreads();
        #pragma unroll
        for (int ks = 0; ks < 2; ks++) {
            int k0 = ks * 8;
            unsigned bfr[2][2];
            #pragma unroll
            for (int nt = 0; nt < 2; nt++) {
                int c = h*32 + n0 + nt*8 + g;
                bfr[nt][0] = v_s[k0 + tig][c];
                bfr[nt][1] = v_s[k0 + tig + 4][c];
            }
            #pragma unroll
            for (int mt = 0; mt < 4; mt++) {
                int r = mt*16 + g;
                unsigned a0 = qk_s[h][r    ][k0 + tig];
                unsigned a1 = qk_s[h][r + 8][k0 + tig];
                unsigned a2 = qk_s[h][r    ][k0 + tig + 4];
                unsigned a3 = qk_s[h][r + 8][k0 + tig + 4];
                mma8(acc[mt][0], a0, a1, a2, a3, bfr[0][0], bfr[0][1]);
                mma8(acc[mt][1], a0, a1, a2, a3, bfr[1][0], bfr[1][1]);
            }
        }
    }

    __syncthreads();
    float* out_s = (float*)&qk_s[0][0][0];   // [i][hd] stride 129
    #pragma unroll
    for (int mt = 0; mt < 4; mt++) {
        int r = mt*16 + g;
        #pragma unroll
        for (int nt = 0; nt < 2; nt++) {
            int c = h*32 + n0 + nt*8 + tig*2;
            out_s[ r     *129 + c    ] = acc[mt][nt][0];
            out_s[ r     *129 + c + 1] = acc[mt][nt][1];
            out_s[(r + 8)*129 + c    ] = acc[mt][nt][2];
            out_s[(r + 8)*129 + c + 1] = acc[mt][nt][3];
        }
    }
    __syncthreads();
    #pragma unroll
    for (int r2 = 0; r2 < 32; r2++) {
        int idx = t + r2*256, c = idx >> 6, ii = idx & 63;
        long p = ((long)b*HID_ + c) * N_ + i0 + ii;
        g_o2[p] += out_s[ii*129 + c];
    }
}

// =================================================================
// Kernel DLN (fused): y = W_out (256x128) @ o2 + b_out, then LayerNorm
// over channels, written directly to d_out. block: 256o x 32i, K=128.
// =================================================================
__global__ void __launch_bounds__(256) kDLN(const float* __restrict__ W,
                                            const float* __restrict__ bias,
                                            const float* __restrict__ gam,
                                            float* __restrict__ out) {
    int it = blockIdx.x, b = blockIdx.y;
    int i0 = it * 32, t = threadIdx.x;
    __shared__ float W_s[8][260];
    __shared__ float X_s[8][36];
    __shared__ float red_s[32][33];
    __shared__ float red_q[32][33];
    __shared__ float mv[32][2];

    int og = t >> 3, ig = t & 7;          // thread: 8 o (og*8..), 4 i (ig*4..)
    const float* xb = g_o2 + (long)b * HID_ * N_;

    float bo[8], ga[8];
    #pragma unroll
    for (int j = 0; j < 8; j++) { bo[j] = bias[og*8+j]; ga[j] = gam[og*8+j]; }

    // staging index sets
    int w_o = t >> 1, w_kq = t & 1;       // W: o = w_o(+128r), kquad
    int x_k = t >> 5, x_i = t & 31;       // X: k row, i col

    float acc[8][4] = {};
    for (int kc = 0; kc < 16; kc++) {
        int k0 = kc * 8;
        if (kc) __syncthreads();
        #pragma unroll
        for (int r = 0; r < 2; r++) {
            float4 wv = *(const float4*)(W + (long)(w_o + 128*r) * HID_ + k0 + w_kq*4);
            const float* wf = (const float*)&wv;
            #pragma unroll
            for (int j = 0; j < 4; j++) W_s[w_kq*4+j][w_o + 128*r] = wf[j];
        }
        X_s[x_k][x_i] = xb[(long)(k0 + x_k) * N_ + i0 + x_i];
        __syncthreads();
        #pragma unroll
        for (int k = 0; k < 8; k++) {
            float4 w0 = *(float4*)&W_s[k][og*8];
            float4 w1 = *(float4*)&W_s[k][og*8 + 4];
            float4 x4 = *(float4*)&X_s[k][ig*4];
            const float* wf0 = (const float*)&w0;
            const float* wf1 = (const float*)&w1;
            const float* xf  = (const float*)&x4;
            #pragma unroll
            for (int j = 0; j < 4; j++)
                #pragma unroll
                for (int ii = 0; ii < 4; ii++) {
                    acc[j  ][ii] += wf0[j] * xf[ii];
                    acc[j+4][ii] += wf1[j] * xf[ii];
                }
        }
    }
    // bias
    #pragma unroll
    for (int j = 0; j < 8; j++)
        #pragma unroll
        for (int ii = 0; ii < 4; ii++) acc[j][ii] += bo[j];

    // LN reduce across 32 og-groups per i
    __syncthreads();
    #pragma unroll
    for (int ii = 0; ii < 4; ii++) {
        float s = 0.f, q = 0.f;
        #pragma unroll
        for (int j = 0; j < 8; j++) { s += acc[j][ii]; q += acc[j][ii]*acc[j][ii]; }
        red_s[ig*4+ii][og] = s;
        red_q[ig*4+ii][og] = q;
    }
    __syncthreads();
    if (t < 32) {
        float s = 0.f, q = 0.f;
        #pragma unroll
        for (int o = 0; o < 32; o++) { s += red_s[t][o]; q += red_q[t][o]; }
        float mean = s * (1.f / DIM_);
        float var  = q * (1.f / DIM_) - mean * mean;
        mv[t][0] = mean;
        mv[t][1] = rsqrtf(var + EPS_);
    }
    __syncthreads();
    float mloc[4], rloc[4];
    #pragma unroll
    for (int ii = 0; ii < 4; ii++) { mloc[ii] = mv[ig*4+ii][0]; rloc[ii] = mv[ig*4+ii][1]; }
    #pragma unroll
    for (int j = 0; j < 8; j++) {
        float4 o4;
        float* of = (float*)&o4;
        #pragma unroll
        for (int ii = 0; ii < 4; ii++)
            of[ii] = (acc[j][ii] - mloc[ii]) * rloc[ii] * ga[j];
        *(float4*)(out + ((long)b*DIM_ + og*8 + j) * N_ + i0 + ig*4) = o4;
    }
}

// =================================================================
extern "C" void kernel_launch(void* const* d_in, const int* in_sizes, int n_in,
                              void* d_out, int out_size) {
    const float* x     = (const float*)d_in[0];
    const float* ind   = (const float*)d_in[1];
    const float* Wqkv  = (const float*)d_in[2];
    const float* Wind  = (const float*)d_in[3];
    const float* Wout  = (const float*)d_in[4];
    const float* bout  = (const float*)d_in[5];
    const float* gam   = (const float*)d_in[6];
    float* out = (float*)d_out;

    kA  <<<dim3(16, 3, B_), 256>>>(Wqkv, x);
    kK  <<<dim3(HID_, B_), 256>>>();
    kKV <<<dim3(B_*H_), 256>>>();
    kLin<<<dim3(8, H_, B_), 128>>>();
    kC  <<<dim3(16, B_), 256>>>(ind, Wind);
    kDLN<<<dim3(32, B_), 256>>>(Wout, bout, gam, out);
}

// round 5
// speedup vs baseline: 1.7381x; 1.2539x over previous
#include <cuda_runtime.h>

#define B_    8
#define N_    1024
#define DIM_  256
#define H_    4
#define DH_   32
#define HID_  128
#define QKV_  384
#define INDC_ 5
#define SCALE_ 0.17677669529663687f
#define EPS_  1e-5f

// ---------------- scratch ----------------
__device__ float g_qkv[B_*QKV_*N_];   // q raw, k softmaxed in place, v raw
__device__ float g_KV [B_*H_*DH_*DH_];// KV[b][h][e][d]
__device__ float g_o2 [B_*HID_*N_];   // attention output, hd-major: [b][hd][i]

__device__ __forceinline__ unsigned tf32u(float f) {
    unsigned u; asm("cvt.rna.tf32.f32 %0, %1;" : "=r"(u) : "f"(f)); return u;
}
__device__ __forceinline__ uint2 split_tf32(float v) {
    unsigned hi = tf32u(v);
    float r = v - __uint_as_float(hi);
    return make_uint2(hi, tf32u(r));
}
__device__ __forceinline__ void mma8(float* c,
                                     unsigned a0, unsigned a1, unsigned a2, unsigned a3,
                                     unsigned b0, unsigned b1) {
    asm volatile("mma.sync.aligned.m16n8k8.row.col.f32.tf32.tf32.f32 "
                 "{%0,%1,%2,%3}, {%4,%5,%6,%7}, {%8,%9}, {%0,%1,%2,%3};\n"
                 : "+f"(c[0]), "+f"(c[1]), "+f"(c[2]), "+f"(c[3])
                 : "r"(a0), "r"(a1), "r"(a2), "r"(a3), "r"(b0), "r"(b1));
}

// =================================================================
// Kernel A (tf32 split-MMA): qkv[b] = W_qkv (384x256) @ x[b] (256x1024)
// =================================================================
__global__ void __launch_bounds__(256) kA(const float* __restrict__ W,
                                          const float* __restrict__ x) {
    int i0 = blockIdx.x * 64, o0 = blockIdx.y * 128, b = blockIdx.z;
    __shared__ unsigned A_s[16][132][2];
    __shared__ unsigned B_s[16][68][2];
    int t = threadIdx.x, warp = t >> 5, lane = t & 31;
    int g = lane >> 2, tig = lane & 3;
    int wm = warp >> 1, wn = warp & 1;
    const float* xb = x + (long)b * DIM_ * N_;

    int aq = t & 3, am = t >> 2;
    int bq = t & 15, bk = t >> 4;

    float4 pa[2], pb;
    #pragma unroll
    for (int r = 0; r < 2; r++)
        pa[r] = *(const float4*)(W + (o0 + am + 64*r) * DIM_ + aq*4);
    pb = *(const float4*)(xb + bk * N_ + i0 + bq*4);

    float acc[2][4][4];
    #pragma unroll
    for (int mt = 0; mt < 2; mt++)
        #pragma unroll
        for (int nt = 0; nt < 4; nt++)
            #pragma unroll
            for (int z = 0; z < 4; z++) acc[mt][nt][z] = 0.f;

    for (int c = 0; c < 16; c++) {
        if (c) __syncthreads();
        #pragma unroll
        for (int r = 0; r < 2; r++) {
            const float* pv = (const float*)&pa[r];
            #pragma unroll
            for (int j = 0; j < 4; j++)
                *(uint2*)&A_s[aq*4+j][am + 64*r][0] = split_tf32(pv[j]);
        }
        {
            const float* pv = (const float*)&pb;
            #pragma unroll
            for (int j = 0; j < 4; j++)
                *(uint2*)&B_s[bk][bq*4+j][0] = split_tf32(pv[j]);
        }
        if (c + 1 < 16) {
            int k0n = (c + 1) * 16;
            #pragma unroll
            for (int r = 0; r < 2; r++)
                pa[r] = *(const float4*)(W + (o0 + am + 64*r) * DIM_ + k0n + aq*4);
            pb = *(const float4*)(xb + (k0n + bk) * N_ + i0 + bq*4);
        }
        __syncthreads();
        #pragma unroll
        for (int ks = 0; ks < 2; ks++) {
            int k8 = ks * 8;
            uint2 Bf[4][2];
            #pragma unroll
            for (int nt = 0; nt < 4; nt++) {
                int cn = wn*32 + nt*8 + g;
                Bf[nt][0] = *(uint2*)&B_s[k8 + tig    ][cn][0];
                Bf[nt][1] = *(uint2*)&B_s[k8 + tig + 4][cn][0];
            }
            #pragma unroll
            for (int mt = 0; mt < 2; mt++) {
                int rm = wm*32 + mt*16 + g;
                uint2 A0 = *(uint2*)&A_s[k8 + tig    ][rm    ][0];
                uint2 A1 = *(uint2*)&A_s[k8 + tig    ][rm + 8][0];
                uint2 A2 = *(uint2*)&A_s[k8 + tig + 4][rm    ][0];
                uint2 A3 = *(uint2*)&A_s[k8 + tig + 4][rm + 8][0];
                #pragma unroll
                for (int nt = 0; nt < 4; nt++) {
                    mma8(acc[mt][nt], A0.x, A1.x, A2.x, A3.x, Bf[nt][0].x, Bf[nt][1].x);
                    mma8(acc[mt][nt], A0.x, A1.x, A2.x, A3.x, Bf[nt][0].y, Bf[nt][1].y);
                    mma8(acc[mt][nt], A0.y, A1.y, A2.y, A3.y, Bf[nt][0].x, Bf[nt][1].x);
                }
            }
        }
    }
    #pragma unroll
    for (int mt = 0; mt < 2; mt++) {
        int row = o0 + wm*32 + mt*16 + g;
        #pragma unroll
        for (int nt = 0; nt < 4; nt++) {
            int col = i0 + wn*32 + nt*8 + tig*2;
            *(float2*)(g_qkv + ((long)b*QKV_ + row    ) * N_ + col) =
                make_float2(acc[mt][nt][0], acc[mt][nt][1]);
            *(float2*)(g_qkv + ((long)b*QKV_ + row + 8) * N_ + col) =
                make_float2(acc[mt][nt][2], acc[mt][nt][3]);
        }
    }
}

// =================================================================
// Kernel K: softmax over n (1024) of each k row, in place.
// =================================================================
__global__ void __launch_bounds__(256) kK() {
    int row = blockIdx.x, b = blockIdx.y;
    float* p = g_qkv + ((long)b*QKV_ + HID_ + row) * N_;
    int t = threadIdx.x;
    __shared__ float red[8];
    float4 v = *(const float4*)(p + t*4);
    float m = fmaxf(fmaxf(v.x, v.y), fmaxf(v.z, v.w));
    #pragma unroll
    for (int o = 16; o; o >>= 1) m = fmaxf(m, __shfl_xor_sync(0xffffffffu, m, o));
    if ((t & 31) == 0) red[t >> 5] = m;
    __syncthreads();
    m = red[0];
    #pragma unroll
    for (int w = 1; w < 8; w++) m = fmaxf(m, red[w]);
    float e0 = __expf(v.x - m), e1 = __expf(v.y - m);
    float e2 = __expf(v.z - m), e3 = __expf(v.w - m);
    float s = e0 + e1 + e2 + e3;
    #pragma unroll
    for (int o = 16; o; o >>= 1) s += __shfl_xor_sync(0xffffffffu, s, o);
    __syncthreads();
    if ((t & 31) == 0) red[t >> 5] = s;
    __syncthreads();
    float tot = 0.f;
    #pragma unroll
    for (int w = 0; w < 8; w++) tot += red[w];
    float inv = 1.f / tot;
    *(float4*)(p + t*4) = make_float4(e0*inv, e1*inv, e2*inv, e3*inv);
}

// =================================================================
// Kernel KV (j-split x8): KV[b][h][e][d] += sum_{j in chunk} k[e][j]*v[d][j]
// grid (32 bh, 8 js). g_KV pre-zeroed by memset node.
// =================================================================
__global__ void __launch_bounds__(256) kKV() {
    int bh = blockIdx.x; int b = bh >> 2, h = bh & 3;
    int jbase = blockIdx.y * 128;
    __shared__ float ksm[32][33], vsm[32][33];
    int t = threadIdx.x;
    int e = t >> 3, d0 = (t & 7) * 4;
    float acc[4] = {};
    const float* kbase = g_qkv + ((long)b*QKV_ + HID_   + h*DH_) * N_;
    const float* vbase = g_qkv + ((long)b*QKV_ + 2*HID_ + h*DH_) * N_;
    for (int jc = 0; jc < 4; jc++) {
        int j0 = jbase + jc * 32;
        if (jc) __syncthreads();
        {
            int ee = t >> 3, j4 = t & 7;
            float4 kv = *(const float4*)(kbase + ee * N_ + j0 + j4*4);
            ksm[ee][j4*4+0] = kv.x; ksm[ee][j4*4+1] = kv.y;
            ksm[ee][j4*4+2] = kv.z; ksm[ee][j4*4+3] = kv.w;
            float4 vv = *(const float4*)(vbase + ee * N_ + j0 + j4*4);
            vsm[ee][j4*4+0] = vv.x; vsm[ee][j4*4+1] = vv.y;
            vsm[ee][j4*4+2] = vv.z; vsm[ee][j4*4+3] = vv.w;
        }
        __syncthreads();
        #pragma unroll 8
        for (int jj = 0; jj < 32; jj++) {
            float kk = ksm[e][jj];
            acc[0] += kk * vsm[d0+0][jj];
            acc[1] += kk * vsm[d0+1][jj];
            acc[2] += kk * vsm[d0+2][jj];
            acc[3] += kk * vsm[d0+3][jj];
        }
    }
    float* dst = g_KV + ((long)bh*DH_ + e) * DH_ + d0;
    atomicAdd(dst+0, acc[0]); atomicAdd(dst+1, acc[1]);
    atomicAdd(dst+2, acc[2]); atomicAdd(dst+3, acc[3]);
}

// =================================================================
// Kernel Lin (fused q-softmax, d-split x2):
//   o2[b][h*32+dh*16+d][i] = (SCALE/sum) * sum_e exp(q-max) * KV[e][d]
// grid (8 i-tiles, 8 h*2+dh, 8 b), 128 threads
// =================================================================
__global__ void __launch_bounds__(128) kLin() {
    int it = blockIdx.x, hy = blockIdx.y, b = blockIdx.z;
    int h = hy >> 1, dh = (hy & 1) * 16;
    int i0 = it * 128, t = threadIdx.x;
    __shared__ float q_s[32][129];
    __shared__ float kv_s[32][17];
    for (int e = 0; e < 32; e++)
        q_s[e][t] = g_qkv[((long)b*QKV_ + h*DH_ + e) * N_ + i0 + t];
    #pragma unroll
    for (int r = 0; r < 4; r++) {
        int idx = t + r * 128;
        int e = idx >> 4, d = idx & 15;
        kv_s[e][d] = g_KV[(((long)(b*H_ + h))*DH_ + e) * DH_ + dh + d];
    }
    __syncthreads();
    float p[32];
    float m = -1e30f;
    #pragma unroll
    for (int e = 0; e < 32; e++) { p[e] = q_s[e][t]; m = fmaxf(m, p[e]); }
    float s = 0.f;
    #pragma unroll
    for (int e = 0; e < 32; e++) { p[e] = __expf(p[e] - m); s += p[e]; }
    float acc[16] = {};
    #pragma unroll 4
    for (int e = 0; e < 32; e++) {
        float pe = p[e];
        #pragma unroll
        for (int d = 0; d < 16; d++) acc[d] += pe * kv_s[e][d];
    }
    float sc = SCALE_ / s;
    #pragma unroll
    for (int d = 0; d < 16; d++)
        g_o2[((long)b*HID_ + h*DH_ + dh + d) * N_ + i0 + t] = acc[d] * sc;
}

// =================================================================
// Kernel C (tf32 MMA, j-split x4): o2 += sum_{j chunk} qk_h[i][j]*v[hd][j]
// grid (16 i-tiles, 4 j-chunks, 8 b), 256 threads
// =================================================================
__global__ void __launch_bounds__(256) kC(const float* __restrict__ ind,
                                          const float* __restrict__ Wind) {
    int it = blockIdx.x, jchunk = blockIdx.y, b = blockIdx.z;
    int i0 = it * 64, jt0 = jchunk * 16, t = threadIdx.x;
    __shared__ unsigned qk_s[4][64][38];
    __shared__ unsigned v_s[16][136];

    int warp = t >> 5, lane = t & 31;
    int h  = warp >> 1;
    int n0 = (warp & 1) * 16;
    int g  = lane >> 2, tig = lane & 3;

    float w[4][5];
    #pragma unroll
    for (int hh = 0; hh < 4; hh++)
        #pragma unroll
        for (int c = 0; c < 5; c++) w[hh][c] = Wind[hh*INDC_ + c];

    int s_ii = t >> 2, s_j4 = (t & 3) * 4;
    int v_hd = t >> 2, v_jq = t & 3;
    const float* indb = ind + ((long)b * INDC_ << 20);
    const float* vbase = g_qkv + ((long)b*QKV_ + 2*HID_) * N_;

    float acc[4][2][4];
    #pragma unroll
    for (int mt = 0; mt < 4; mt++)
        #pragma unroll
        for (int nt = 0; nt < 2; nt++)
            #pragma unroll
            for (int z = 0; z < 4; z++) acc[mt][nt][z] = 0.f;

    float4 pind[5], pv[2];
    {
        int j0 = jt0 * 16;
        #pragma unroll
        for (int c = 0; c < 5; c++)
            pind[c] = *(const float4*)(indb + ((long)c << 20) + (long)(i0 + s_ii) * N_ + j0 + s_j4);
        #pragma unroll
        for (int r = 0; r < 2; r++)
            pv[r] = *(const float4*)(vbase + (long)(v_hd + 64*r) * N_ + j0 + v_jq*4);
    }

    for (int jt = 0; jt < 16; jt++) {
        if (jt) __syncthreads();
        #pragma unroll
        for (int r = 0; r < 2; r++) {
            const float* pf = (const float*)&pv[r];
            int hd = v_hd + 64*r;
            #pragma unroll
            for (int u = 0; u < 4; u++)
                v_s[v_jq*4+u][hd] = tf32u(pf[u]);
        }
        #pragma unroll
        for (int hh = 0; hh < 4; hh++) {
            float o0 = 0.f, o1 = 0.f, o2v = 0.f, o3 = 0.f;
            #pragma unroll
            for (int c = 0; c < 5; c++) {
                float wc = w[hh][c];
                o0 += wc * pind[c].x; o1 += wc * pind[c].y;
                o2v += wc * pind[c].z; o3 += wc * pind[c].w;
            }
            qk_s[hh][s_ii][s_j4+0] = tf32u(o0);
            qk_s[hh][s_ii][s_j4+1] = tf32u(o1);
            qk_s[hh][s_ii][s_j4+2] = tf32u(o2v);
            qk_s[hh][s_ii][s_j4+3] = tf32u(o3);
        }
        if (jt + 1 < 16) {
            int j0n = (jt0 + jt + 1) * 16;
            #pragma unroll
            for (int c = 0; c < 5; c++)
                pind[c] = *(const float4*)(indb + ((long)c << 20) + (long)(i0 + s_ii) * N_ + j0n + s_j4);
            #pragma unroll
            for (int r = 0; r < 2; r++)
                pv[r] = *(const float4*)(vbase + (long)(v_hd + 64*r) * N_ + j0n + v_jq*4);
        }
        __syncthreads();
        #pragma unroll
        for (int ks = 0; ks < 2; ks++) {
            int k0 = ks * 8;
            unsigned bfr[2][2];
            #pragma unroll
            for (int nt = 0; nt < 2; nt++) {
                int c = h*32 + n0 + nt*8 + g;
                bfr[nt][0] = v_s[k0 + tig][c];
                bfr[nt][1] = v_s[k0 + tig + 4][c];
            }
            #pragma unroll
            for (int mt = 0; mt < 4; mt++) {
                int r = mt*16 + g;
                unsigned a0 = qk_s[h][r    ][k0 + tig];
                unsigned a1 = qk_s[h][r + 8][k0 + tig];
                unsigned a2 = qk_s[h][r    ][k0 + tig + 4];
                unsigned a3 = qk_s[h][r + 8][k0 + tig + 4];
                mma8(acc[mt][0], a0, a1, a2, a3, bfr[0][0], bfr[0][1]);
                mma8(acc[mt][1], a0, a1, a2, a3, bfr[1][0], bfr[1][1]);
            }
        }
    }

    __syncthreads();
    float* out_s = (float*)&qk_s[0][0][0];
    #pragma unroll
    for (int mt = 0; mt < 4; mt++) {
        int r = mt*16 + g;
        #pragma unroll
        for (int nt = 0; nt < 2; nt++) {
            int c = h*32 + n0 + nt*8 + tig*2;
            out_s[ r     *129 + c    ] = acc[mt][nt][0];
            out_s[ r     *129 + c + 1] = acc[mt][nt][1];
            out_s[(r + 8)*129 + c    ] = acc[mt][nt][2];
            out_s[(r + 8)*129 + c + 1] = acc[mt][nt][3];
        }
    }
    __syncthreads();
    #pragma unroll
    for (int r2 = 0; r2 < 32; r2++) {
        int idx = t + r2*256, c = idx >> 6, ii = idx & 63;
        long p = ((long)b*HID_ + c) * N_ + i0 + ii;
        atomicAdd(&g_o2[p], out_s[ii*129 + c]);
    }
}

// =================================================================
// Kernel DLN (fused): y = W_out @ o2 + b_out, then channel LayerNorm
// =================================================================
__global__ void __launch_bounds__(256) kDLN(const float* __restrict__ W,
                                            const float* __restrict__ bias,
                                            const float* __restrict__ gam,
                                            float* __restrict__ out) {
    int it = blockIdx.x, b = blockIdx.y;
    int i0 = it * 32, t = threadIdx.x;
    __shared__ float W_s[8][260];
    __shared__ float X_s[8][36];
    __shared__ float red_s[32][33];
    __shared__ float red_q[32][33];
    __shared__ float mv[32][2];

    int og = t >> 3, ig = t & 7;
    const float* xb = g_o2 + (long)b * HID_ * N_;

    float bo[8], ga[8];
    #pragma unroll
    for (int j = 0; j < 8; j++) { bo[j] = bias[og*8+j]; ga[j] = gam[og*8+j]; }

    int w_o = t >> 1, w_kq = t & 1;
    int x_k = t >> 5, x_i = t & 31;

    float acc[8][4] = {};
    for (int kc = 0; kc < 16; kc++) {
        int k0 = kc * 8;
        if (kc) __syncthreads();
        #pragma unroll
        for (int r = 0; r < 2; r++) {
            float4 wv = *(const float4*)(W + (long)(w_o + 128*r) * HID_ + k0 + w_kq*4);
            const float* wf = (const float*)&wv;
            #pragma unroll
            for (int j = 0; j < 4; j++) W_s[w_kq*4+j][w_o + 128*r] = wf[j];
        }
        X_s[x_k][x_i] = xb[(long)(k0 + x_k) * N_ + i0 + x_i];
        __syncthreads();
        #pragma unroll
        for (int k = 0; k < 8; k++) {
            float4 w0 = *(float4*)&W_s[k][og*8];
            float4 w1 = *(float4*)&W_s[k][og*8 + 4];
            float4 x4 = *(float4*)&X_s[k][ig*4];
            const float* wf0 = (const float*)&w0;
            const float* wf1 = (const float*)&w1;
            const float* xf  = (const float*)&x4;
            #pragma unroll
            for (int j = 0; j < 4; j++)
                #pragma unroll
                for (int ii = 0; ii < 4; ii++) {
                    acc[j  ][ii] += wf0[j] * xf[ii];
                    acc[j+4][ii] += wf1[j] * xf[ii];
                }
        }
    }
    #pragma unroll
    for (int j = 0; j < 8; j++)
        #pragma unroll
        for (int ii = 0; ii < 4; ii++) acc[j][ii] += bo[j];

    __syncthreads();
    #pragma unroll
    for (int ii = 0; ii < 4; ii++) {
        float s = 0.f, q = 0.f;
        #pragma unroll
        for (int j = 0; j < 8; j++) { s += acc[j][ii]; q += acc[j][ii]*acc[j][ii]; }
        red_s[ig*4+ii][og] = s;
        red_q[ig*4+ii][og] = q;
    }
    __syncthreads();
    if (t < 32) {
        float s = 0.f, q = 0.f;
        #pragma unroll
        for (int o = 0; o < 32; o++) { s += red_s[t][o]; q += red_q[t][o]; }
        float mean = s * (1.f / DIM_);
        float var  = q * (1.f / DIM_) - mean * mean;
        mv[t][0] = mean;
        mv[t][1] = rsqrtf(var + EPS_);
    }
    __syncthreads();
    float mloc[4], rloc[4];
    #pragma unroll
    for (int ii = 0; ii < 4; ii++) { mloc[ii] = mv[ig*4+ii][0]; rloc[ii] = mv[ig*4+ii][1]; }
    #pragma unroll
    for (int j = 0; j < 8; j++) {
        float4 o4;
        float* of = (float*)&o4;
        #pragma unroll
        for (int ii = 0; ii < 4; ii++)
            of[ii] = (acc[j][ii] - mloc[ii]) * rloc[ii] * ga[j];
        *(float4*)(out + ((long)b*DIM_ + og*8 + j) * N_ + i0 + ig*4) = o4;
    }
}

// =================================================================
extern "C" void kernel_launch(void* const* d_in, const int* in_sizes, int n_in,
                              void* d_out, int out_size) {
    const float* x     = (const float*)d_in[0];
    const float* ind   = (const float*)d_in[1];
    const float* Wqkv  = (const float*)d_in[2];
    const float* Wind  = (const float*)d_in[3];
    const float* Wout  = (const float*)d_in[4];
    const float* bout  = (const float*)d_in[5];
    const float* gam   = (const float*)d_in[6];
    float* out = (float*)d_out;

    void* kvptr = nullptr;
    cudaGetSymbolAddress(&kvptr, g_KV);

    kA  <<<dim3(16, 3, B_), 256>>>(Wqkv, x);
    kK  <<<dim3(HID_, B_), 256>>>();
    cudaMemsetAsync(kvptr, 0, sizeof(float)*B_*H_*DH_*DH_, 0);
    kKV <<<dim3(B_*H_, 8), 256>>>();
    kLin<<<dim3(8, 8, B_), 128>>>();
    kC  <<<dim3(16, 4, B_), 256>>>(ind, Wind);
    kDLN<<<dim3(32, B_), 256>>>(Wout, bout, gam, out);
}

// round 6
// speedup vs baseline: 1.7662x; 1.0162x over previous
#include <cuda_runtime.h>

#define B_    8
#define N_    1024
#define DIM_  256
#define H_    4
#define DH_   32
#define HID_  128
#define QKV_  384
#define INDC_ 5
#define SCALE_ 0.17677669529663687f
#define EPS_  1e-5f

// ---------------- scratch ----------------
__device__ float g_qkv[B_*QKV_*N_];   // q raw, k softmaxed in place, v raw
__device__ float g_KV [B_*H_*DH_*DH_];// KV[b][h][e][d]
__device__ float g_o2 [B_*HID_*N_];   // indicator-term output (atomic accum)
__device__ float g_lin[B_*HID_*N_];   // linear-term output

__device__ __forceinline__ unsigned tf32u(float f) {
    unsigned u; asm("cvt.rna.tf32.f32 %0, %1;" : "=r"(u) : "f"(f)); return u;
}
__device__ __forceinline__ uint2 split_tf32(float v) {
    unsigned hi = tf32u(v);
    float r = v - __uint_as_float(hi);
    return make_uint2(hi, tf32u(r));
}
__device__ __forceinline__ void mma8(float* c,
                                     unsigned a0, unsigned a1, unsigned a2, unsigned a3,
                                     unsigned b0, unsigned b1) {
    asm volatile("mma.sync.aligned.m16n8k8.row.col.f32.tf32.tf32.f32 "
                 "{%0,%1,%2,%3}, {%4,%5,%6,%7}, {%8,%9}, {%0,%1,%2,%3};\n"
                 : "+f"(c[0]), "+f"(c[1]), "+f"(c[2]), "+f"(c[3])
                 : "r"(a0), "r"(a1), "r"(a2), "r"(a3), "r"(b0), "r"(b1));
}

// =================================================================
// Kernel A (tf32 split-MMA): qkv[b] = W_qkv (384x256) @ x[b] (256x1024)
// =================================================================
__global__ void __launch_bounds__(256) kA(const float* __restrict__ W,
                                          const float* __restrict__ x) {
    int i0 = blockIdx.x * 64, o0 = blockIdx.y * 128, b = blockIdx.z;
    __shared__ unsigned A_s[16][132][2];
    __shared__ unsigned B_s[16][68][2];
    int t = threadIdx.x, warp = t >> 5, lane = t & 31;
    int g = lane >> 2, tig = lane & 3;
    int wm = warp >> 1, wn = warp & 1;
    const float* xb = x + (long)b * DIM_ * N_;

    int aq = t & 3, am = t >> 2;
    int bq = t & 15, bk = t >> 4;

    float4 pa[2], pb;
    #pragma unroll
    for (int r = 0; r < 2; r++)
        pa[r] = *(const float4*)(W + (o0 + am + 64*r) * DIM_ + aq*4);
    pb = *(const float4*)(xb + bk * N_ + i0 + bq*4);

    float acc[2][4][4];
    #pragma unroll
    for (int mt = 0; mt < 2; mt++)
        #pragma unroll
        for (int nt = 0; nt < 4; nt++)
            #pragma unroll
            for (int z = 0; z < 4; z++) acc[mt][nt][z] = 0.f;

    for (int c = 0; c < 16; c++) {
        if (c) __syncthreads();
        #pragma unroll
        for (int r = 0; r < 2; r++) {
            const float* pv = (const float*)&pa[r];
            #pragma unroll
            for (int j = 0; j < 4; j++)
                *(uint2*)&A_s[aq*4+j][am + 64*r][0] = split_tf32(pv[j]);
        }
        {
            const float* pv = (const float*)&pb;
            #pragma unroll
            for (int j = 0; j < 4; j++)
                *(uint2*)&B_s[bk][bq*4+j][0] = split_tf32(pv[j]);
        }
        if (c + 1 < 16) {
            int k0n = (c + 1) * 16;
            #pragma unroll
            for (int r = 0; r < 2; r++)
                pa[r] = *(const float4*)(W + (o0 + am + 64*r) * DIM_ + k0n + aq*4);
            pb = *(const float4*)(xb + (k0n + bk) * N_ + i0 + bq*4);
        }
        __syncthreads();
        #pragma unroll
        for (int ks = 0; ks < 2; ks++) {
            int k8 = ks * 8;
            uint2 Bf[4][2];
            #pragma unroll
            for (int nt = 0; nt < 4; nt++) {
                int cn = wn*32 + nt*8 + g;
                Bf[nt][0] = *(uint2*)&B_s[k8 + tig    ][cn][0];
                Bf[nt][1] = *(uint2*)&B_s[k8 + tig + 4][cn][0];
            }
            #pragma unroll
            for (int mt = 0; mt < 2; mt++) {
                int rm = wm*32 + mt*16 + g;
                uint2 A0 = *(uint2*)&A_s[k8 + tig    ][rm    ][0];
                uint2 A1 = *(uint2*)&A_s[k8 + tig    ][rm + 8][0];
                uint2 A2 = *(uint2*)&A_s[k8 + tig + 4][rm    ][0];
                uint2 A3 = *(uint2*)&A_s[k8 + tig + 4][rm + 8][0];
                #pragma unroll
                for (int nt = 0; nt < 4; nt++) {
                    mma8(acc[mt][nt], A0.x, A1.x, A2.x, A3.x, Bf[nt][0].x, Bf[nt][1].x);
                    mma8(acc[mt][nt], A0.x, A1.x, A2.x, A3.x, Bf[nt][0].y, Bf[nt][1].y);
                    mma8(acc[mt][nt], A0.y, A1.y, A2.y, A3.y, Bf[nt][0].x, Bf[nt][1].x);
                }
            }
        }
    }
    #pragma unroll
    for (int mt = 0; mt < 2; mt++) {
        int row = o0 + wm*32 + mt*16 + g;
        #pragma unroll
        for (int nt = 0; nt < 4; nt++) {
            int col = i0 + wn*32 + nt*8 + tig*2;
            *(float2*)(g_qkv + ((long)b*QKV_ + row    ) * N_ + col) =
                make_float2(acc[mt][nt][0], acc[mt][nt][1]);
            *(float2*)(g_qkv + ((long)b*QKV_ + row + 8) * N_ + col) =
                make_float2(acc[mt][nt][2], acc[mt][nt][3]);
        }
    }
}

// =================================================================
// Kernel K: softmax over n (1024) of each k row, in place.
// =================================================================
__global__ void __launch_bounds__(256) kK() {
    int row = blockIdx.x, b = blockIdx.y;
    float* p = g_qkv + ((long)b*QKV_ + HID_ + row) * N_;
    int t = threadIdx.x;
    __shared__ float red[8];
    float4 v = *(const float4*)(p + t*4);
    float m = fmaxf(fmaxf(v.x, v.y), fmaxf(v.z, v.w));
    #pragma unroll
    for (int o = 16; o; o >>= 1) m = fmaxf(m, __shfl_xor_sync(0xffffffffu, m, o));
    if ((t & 31) == 0) red[t >> 5] = m;
    __syncthreads();
    m = red[0];
    #pragma unroll
    for (int w = 1; w < 8; w++) m = fmaxf(m, red[w]);
    float e0 = __expf(v.x - m), e1 = __expf(v.y - m);
    float e2 = __expf(v.z - m), e3 = __expf(v.w - m);
    float s = e0 + e1 + e2 + e3;
    #pragma unroll
    for (int o = 16; o; o >>= 1) s += __shfl_xor_sync(0xffffffffu, s, o);
    __syncthreads();
    if ((t & 31) == 0) red[t >> 5] = s;
    __syncthreads();
    float tot = 0.f;
    #pragma unroll
    for (int w = 0; w < 8; w++) tot += red[w];
    float inv = 1.f / tot;
    *(float4*)(p + t*4) = make_float4(e0*inv, e1*inv, e2*inv, e3*inv);
}

// =================================================================
// Kernel KV (j-split x8): KV += sum_{j chunk} k[e][j]*v[d][j]
// =================================================================
__global__ void __launch_bounds__(256) kKV() {
    int bh = blockIdx.x; int b = bh >> 2, h = bh & 3;
    int jbase = blockIdx.y * 128;
    __shared__ float ksm[32][33], vsm[32][33];
    int t = threadIdx.x;
    int e = t >> 3, d0 = (t & 7) * 4;
    float acc[4] = {};
    const float* kbase = g_qkv + ((long)b*QKV_ + HID_   + h*DH_) * N_;
    const float* vbase = g_qkv + ((long)b*QKV_ + 2*HID_ + h*DH_) * N_;
    for (int jc = 0; jc < 4; jc++) {
        int j0 = jbase + jc * 32;
        if (jc) __syncthreads();
        {
            int ee = t >> 3, j4 = t & 7;
            float4 kv = *(const float4*)(kbase + ee * N_ + j0 + j4*4);
            ksm[ee][j4*4+0] = kv.x; ksm[ee][j4*4+1] = kv.y;
            ksm[ee][j4*4+2] = kv.z; ksm[ee][j4*4+3] = kv.w;
            float4 vv = *(const float4*)(vbase + ee * N_ + j0 + j4*4);
            vsm[ee][j4*4+0] = vv.x; vsm[ee][j4*4+1] = vv.y;
            vsm[ee][j4*4+2] = vv.z; vsm[ee][j4*4+3] = vv.w;
        }
        __syncthreads();
        #pragma unroll 8
        for (int jj = 0; jj < 32; jj++) {
            float kk = ksm[e][jj];
            acc[0] += kk * vsm[d0+0][jj];
            acc[1] += kk * vsm[d0+1][jj];
            acc[2] += kk * vsm[d0+2][jj];
            acc[3] += kk * vsm[d0+3][jj];
        }
    }
    float* dst = g_KV + ((long)bh*DH_ + e) * DH_ + d0;
    atomicAdd(dst+0, acc[0]); atomicAdd(dst+1, acc[1]);
    atomicAdd(dst+2, acc[2]); atomicAdd(dst+3, acc[3]);
}

// =================================================================
// Kernel Lin (fused q-softmax, d-split x2) -> g_lin
// =================================================================
__global__ void __launch_bounds__(128) kLin() {
    int it = blockIdx.x, hy = blockIdx.y, b = blockIdx.z;
    int h = hy >> 1, dh = (hy & 1) * 16;
    int i0 = it * 128, t = threadIdx.x;
    __shared__ float q_s[32][129];
    __shared__ float kv_s[32][17];
    for (int e = 0; e < 32; e++)
        q_s[e][t] = g_qkv[((long)b*QKV_ + h*DH_ + e) * N_ + i0 + t];
    #pragma unroll
    for (int r = 0; r < 4; r++) {
        int idx = t + r * 128;
        int e = idx >> 4, d = idx & 15;
        kv_s[e][d] = g_KV[(((long)(b*H_ + h))*DH_ + e) * DH_ + dh + d];
    }
    __syncthreads();
    float p[32];
    float m = -1e30f;
    #pragma unroll
    for (int e = 0; e < 32; e++) { p[e] = q_s[e][t]; m = fmaxf(m, p[e]); }
    float s = 0.f;
    #pragma unroll
    for (int e = 0; e < 32; e++) { p[e] = __expf(p[e] - m); s += p[e]; }
    float acc[16] = {};
    #pragma unroll 4
    for (int e = 0; e < 32; e++) {
        float pe = p[e];
        #pragma unroll
        for (int d = 0; d < 16; d++) acc[d] += pe * kv_s[e][d];
    }
    float sc = SCALE_ / s;
    #pragma unroll
    for (int d = 0; d < 16; d++)
        g_lin[((long)b*HID_ + h*DH_ + dh + d) * N_ + i0 + t] = acc[d] * sc;
}

// =================================================================
// Kernel C (tf32 MMA, j-split x4): g_o2 += indicator-term (atomic)
// =================================================================
__global__ void __launch_bounds__(256) kC(const float* __restrict__ ind,
                                          const float* __restrict__ Wind) {
    int it = blockIdx.x, jchunk = blockIdx.y, b = blockIdx.z;
    int i0 = it * 64, jt0 = jchunk * 16, t = threadIdx.x;
    __shared__ unsigned qk_s[4][64][38];
    __shared__ unsigned v_s[16][136];

    int warp = t >> 5, lane = t & 31;
    int h  = warp >> 1;
    int n0 = (warp & 1) * 16;
    int g  = lane >> 2, tig = lane & 3;

    float w[4][5];
    #pragma unroll
    for (int hh = 0; hh < 4; hh++)
        #pragma unroll
        for (int c = 0; c < 5; c++) w[hh][c] = Wind[hh*INDC_ + c];

    int s_ii = t >> 2, s_j4 = (t & 3) * 4;
    int v_hd = t >> 2, v_jq = t & 3;
    const float* indb = ind + ((long)b * INDC_ << 20);
    const float* vbase = g_qkv + ((long)b*QKV_ + 2*HID_) * N_;

    float acc[4][2][4];
    #pragma unroll
    for (int mt = 0; mt < 4; mt++)
        #pragma unroll
        for (int nt = 0; nt < 2; nt++)
            #pragma unroll
            for (int z = 0; z < 4; z++) acc[mt][nt][z] = 0.f;

    float4 pind[5], pv[2];
    {
        int j0 = jt0 * 16;
        #pragma unroll
        for (int c = 0; c < 5; c++)
            pind[c] = *(const float4*)(indb + ((long)c << 20) + (long)(i0 + s_ii) * N_ + j0 + s_j4);
        #pragma unroll
        for (int r = 0; r < 2; r++)
            pv[r] = *(const float4*)(vbase + (long)(v_hd + 64*r) * N_ + j0 + v_jq*4);
    }

    for (int jt = 0; jt < 16; jt++) {
        if (jt) __syncthreads();
        #pragma unroll
        for (int r = 0; r < 2; r++) {
            const float* pf = (const float*)&pv[r];
            int hd = v_hd + 64*r;
            #pragma unroll
            for (int u = 0; u < 4; u++)
                v_s[v_jq*4+u][hd] = tf32u(pf[u]);
        }
        #pragma unroll
        for (int hh = 0; hh < 4; hh++) {
            float o0 = 0.f, o1 = 0.f, o2v = 0.f, o3 = 0.f;
            #pragma unroll
            for (int c = 0; c < 5; c++) {
                float wc = w[hh][c];
                o0 += wc * pind[c].x; o1 += wc * pind[c].y;
                o2v += wc * pind[c].z; o3 += wc * pind[c].w;
            }
            qk_s[hh][s_ii][s_j4+0] = tf32u(o0);
            qk_s[hh][s_ii][s_j4+1] = tf32u(o1);
            qk_s[hh][s_ii][s_j4+2] = tf32u(o2v);
            qk_s[hh][s_ii][s_j4+3] = tf32u(o3);
        }
        if (jt + 1 < 16) {
            int j0n = (jt0 + jt + 1) * 16;
            #pragma unroll
            for (int c = 0; c < 5; c++)
                pind[c] = *(const float4*)(indb + ((long)c << 20) + (long)(i0 + s_ii) * N_ + j0n + s_j4);
            #pragma unroll
            for (int r = 0; r < 2; r++)
                pv[r] = *(const float4*)(vbase + (long)(v_hd + 64*r) * N_ + j0n + v_jq*4);
        }
        __syncthreads();
        #pragma unroll
        for (int ks = 0; ks < 2; ks++) {
            int k0 = ks * 8;
            unsigned bfr[2][2];
            #pragma unroll
            for (int nt = 0; nt < 2; nt++) {
                int c = h*32 + n0 + nt*8 + g;
                bfr[nt][0] = v_s[k0 + tig][c];
                bfr[nt][1] = v_s[k0 + tig + 4][c];
            }
            #pragma unroll
            for (int mt = 0; mt < 4; mt++) {
                int r = mt*16 + g;
                unsigned a0 = qk_s[h][r    ][k0 + tig];
                unsigned a1 = qk_s[h][r + 8][k0 + tig];
                unsigned a2 = qk_s[h][r    ][k0 + tig + 4];
                unsigned a3 = qk_s[h][r + 8][k0 + tig + 4];
                mma8(acc[mt][0], a0, a1, a2, a3, bfr[0][0], bfr[0][1]);
                mma8(acc[mt][1], a0, a1, a2, a3, bfr[1][0], bfr[1][1]);
            }
        }
    }

    __syncthreads();
    float* out_s = (float*)&qk_s[0][0][0];
    #pragma unroll
    for (int mt = 0; mt < 4; mt++) {
        int r = mt*16 + g;
        #pragma unroll
        for (int nt = 0; nt < 2; nt++) {
            int c = h*32 + n0 + nt*8 + tig*2;
            out_s[ r     *129 + c    ] = acc[mt][nt][0];
            out_s[ r     *129 + c + 1] = acc[mt][nt][1];
            out_s[(r + 8)*129 + c    ] = acc[mt][nt][2];
            out_s[(r + 8)*129 + c + 1] = acc[mt][nt][3];
        }
    }
    __syncthreads();
    #pragma unroll
    for (int r2 = 0; r2 < 32; r2++) {
        int idx = t + r2*256, c = idx >> 6, ii = idx & 63;
        long p = ((long)b*HID_ + c) * N_ + i0 + ii;
        atomicAdd(&g_o2[p], out_s[ii*129 + c]);
    }
}

// =================================================================
// Kernel DLN (fused, 512 thr): y = W_out @ (o2+lin) + b_out, then LN
// =================================================================
__global__ void __launch_bounds__(512) kDLN(const float* __restrict__ W,
                                            const float* __restrict__ bias,
                                            const float* __restrict__ gam,
                                            float* __restrict__ out) {
    int it = blockIdx.x, b = blockIdx.y;
    int i0 = it * 32, t = threadIdx.x;
    __shared__ float W_s[8][260];
    __shared__ float X_s[8][36];
    __shared__ float red_s[32][65];
    __shared__ float red_q[32][65];
    __shared__ float mv[32][2];

    int og = t >> 3, ig = t & 7;   // 4 o x 4 i per thread
    float bo[4], ga[4];
    #pragma unroll
    for (int j = 0; j < 4; j++) { bo[j] = bias[og*4+j]; ga[j] = gam[og*4+j]; }

    int w_o = t >> 1, w_kq = t & 1;

    float acc[4][4] = {};
    for (int kc = 0; kc < 16; kc++) {
        int k0 = kc * 8;
        if (kc) __syncthreads();
        {
            float4 wv = *(const float4*)(W + (long)w_o * HID_ + k0 + w_kq*4);
            const float* wf = (const float*)&wv;
            #pragma unroll
            for (int j = 0; j < 4; j++) W_s[w_kq*4+j][w_o] = wf[j];
        }
        if (t < 256) {
            long p = ((long)b*HID_ + k0 + (t>>5)) * N_ + i0 + (t & 31);
            X_s[t>>5][t&31] = g_o2[p] + g_lin[p];
        }
        __syncthreads();
        #pragma unroll
        for (int k = 0; k < 8; k++) {
            float4 w4 = *(float4*)&W_s[k][og*4];
            float4 x4 = *(float4*)&X_s[k][ig*4];
            const float* wf = (const float*)&w4;
            const float* xf = (const float*)&x4;
            #pragma unroll
            for (int j = 0; j < 4; j++)
                #pragma unroll
                for (int ii = 0; ii < 4; ii++)
                    acc[j][ii] += wf[j] * xf[ii];
        }
    }
    #pragma unroll
    for (int j = 0; j < 4; j++)
        #pragma unroll
        for (int ii = 0; ii < 4; ii++) acc[j][ii] += bo[j];

    __syncthreads();
    #pragma unroll
    for (int ii = 0; ii < 4; ii++) {
        float s = 0.f, q = 0.f;
        #pragma unroll
        for (int j = 0; j < 4; j++) { s += acc[j][ii]; q += acc[j][ii]*acc[j][ii]; }
        red_s[ig*4+ii][og] = s;
        red_q[ig*4+ii][og] = q;
    }
    __syncthreads();
    if (t < 32) {
        float s = 0.f, q = 0.f;
        #pragma unroll
        for (int o = 0; o < 64; o++) { s += red_s[t][o]; q += red_q[t][o]; }
        float mean = s * (1.f / DIM_);
        float var  = q * (1.f / DIM_) - mean * mean;
        mv[t][0] = mean;
        mv[t][1] = rsqrtf(var + EPS_);
    }
    __syncthreads();
    float mloc[4], rloc[4];
    #pragma unroll
    for (int ii = 0; ii < 4; ii++) { mloc[ii] = mv[ig*4+ii][0]; rloc[ii] = mv[ig*4+ii][1]; }
    #pragma unroll
    for (int j = 0; j < 4; j++) {
        float4 o4;
        float* of = (float*)&o4;
        #pragma unroll
        for (int ii = 0; ii < 4; ii++)
            of[ii] = (acc[j][ii] - mloc[ii]) * rloc[ii] * ga[j];
        *(float4*)(out + ((long)b*DIM_ + og*4 + j) * N_ + i0 + ig*4) = o4;
    }
}

// =================================================================
extern "C" void kernel_launch(void* const* d_in, const int* in_sizes, int n_in,
                              void* d_out, int out_size) {
    const float* x     = (const float*)d_in[0];
    const float* ind   = (const float*)d_in[1];
    const float* Wqkv  = (const float*)d_in[2];
    const float* Wind  = (const float*)d_in[3];
    const float* Wout  = (const float*)d_in[4];
    const float* bout  = (const float*)d_in[5];
    const float* gam   = (const float*)d_in[6];
    float* out = (float*)d_out;

    // one-time resources (created on the uncaptured correctness call;
    // reused identically on every call -> deterministic, capture-safe)
    static cudaStream_t s1 = nullptr;
    static cudaEvent_t evStart = nullptr, evA = nullptr, evC = nullptr;
    if (!s1) {
        cudaStreamCreateWithFlags(&s1, cudaStreamNonBlocking);
        cudaEventCreateWithFlags(&evStart, cudaEventDisableTiming);
        cudaEventCreateWithFlags(&evA, cudaEventDisableTiming);
        cudaEventCreateWithFlags(&evC, cudaEventDisableTiming);
    }

    void* kvptr = nullptr; cudaGetSymbolAddress(&kvptr, g_KV);
    void* o2ptr = nullptr; cudaGetSymbolAddress(&o2ptr, g_o2);

    // fork s1 off the launch stream
    cudaEventRecord(evStart, 0);
    cudaStreamWaitEvent(s1, evStart, 0);

    // branch B start: zero o2 (independent of kA)
    cudaMemsetAsync(o2ptr, 0, sizeof(float)*B_*HID_*N_, s1);

    // main stream: kA
    kA<<<dim3(16, 3, B_), 256>>>(Wqkv, x);
    cudaEventRecord(evA, 0);

    // branch B: kC after kA
    cudaStreamWaitEvent(s1, evA, 0);
    kC<<<dim3(16, 4, B_), 256, 0, s1>>>(ind, Wind);
    cudaEventRecord(evC, s1);

    // branch A (main stream): kK -> kKV -> kLin
    cudaMemsetAsync(kvptr, 0, sizeof(float)*B_*H_*DH_*DH_, 0);
    kK  <<<dim3(HID_, B_), 256>>>();
    kKV <<<dim3(B_*H_, 8), 256>>>();
    kLin<<<dim3(8, 8, B_), 128>>>();

    // join and finish
    cudaStreamWaitEvent(0, evC, 0);
    kDLN<<<dim3(32, B_), 512>>>(Wout, bout, gam, out);
}

// round 7
// speedup vs baseline: 2.1175x; 1.1989x over previous
#include <cuda_runtime.h>

#define B_    8
#define N_    1024
#define DIM_  256
#define H_    4
#define DH_   32
#define HID_  128
#define QKV_  384
#define INDC_ 5
#define SCALE_ 0.17677669529663687f
#define EPS_  1e-5f

// ---------------- scratch ----------------
__device__ float g_qkv[B_*QKV_*N_];   // q raw, k softmaxed in place, v raw
__device__ float g_KV [B_*H_*DH_*DH_];// KV[b][h][e][d] (atomic accum)
__device__ float g_o2 [B_*HID_*N_];   // indicator-term output (atomic accum)
__device__ float g_lin[B_*HID_*N_];   // linear-term output

__device__ __forceinline__ unsigned tf32u(float f) {
    unsigned u; asm("cvt.rna.tf32.f32 %0, %1;" : "=r"(u) : "f"(f)); return u;
}
__device__ __forceinline__ uint2 split_tf32(float v) {
    unsigned hi = tf32u(v);
    float r = v - __uint_as_float(hi);
    return make_uint2(hi, tf32u(r));
}
__device__ __forceinline__ void mma8(float* c,
                                     unsigned a0, unsigned a1, unsigned a2, unsigned a3,
                                     unsigned b0, unsigned b1) {
    asm volatile("mma.sync.aligned.m16n8k8.row.col.f32.tf32.tf32.f32 "
                 "{%0,%1,%2,%3}, {%4,%5,%6,%7}, {%8,%9}, {%0,%1,%2,%3};\n"
                 : "+f"(c[0]), "+f"(c[1]), "+f"(c[2]), "+f"(c[3])
                 : "r"(a0), "r"(a1), "r"(a2), "r"(a3), "r"(b0), "r"(b1));
}

// =================================================================
// Kernel A (tf32 2-MMA): qkv[b] = W_qkv @ x[b];  D = Wh*xh + Wh*xl
// =================================================================
__global__ void __launch_bounds__(256) kA(const float* __restrict__ W,
                                          const float* __restrict__ x) {
    int i0 = blockIdx.x * 64, o0 = blockIdx.y * 128, b = blockIdx.z;
    __shared__ unsigned A_s[16][136];     // [k][m] hi only, stride 136 (bank-clean)
    __shared__ unsigned B_s[16][68][2];   // [k][n][hi/lo]
    int t = threadIdx.x, warp = t >> 5, lane = t & 31;
    int g = lane >> 2, tig = lane & 3;
    int wm = warp >> 1, wn = warp & 1;
    const float* xb = x + (long)b * DIM_ * N_;

    int aq = t & 3, am = t >> 2;
    int bq = t & 15, bk = t >> 4;

    float4 pa[2], pb;
    #pragma unroll
    for (int r = 0; r < 2; r++)
        pa[r] = *(const float4*)(W + (o0 + am + 64*r) * DIM_ + aq*4);
    pb = *(const float4*)(xb + bk * N_ + i0 + bq*4);

    float acc[2][4][4];
    #pragma unroll
    for (int mt = 0; mt < 2; mt++)
        #pragma unroll
        for (int nt = 0; nt < 4; nt++)
            #pragma unroll
            for (int z = 0; z < 4; z++) acc[mt][nt][z] = 0.f;

    for (int c = 0; c < 16; c++) {
        if (c) __syncthreads();
        #pragma unroll
        for (int r = 0; r < 2; r++) {
            const float* pv = (const float*)&pa[r];
            #pragma unroll
            for (int j = 0; j < 4; j++)
                A_s[aq*4+j][am + 64*r] = tf32u(pv[j]);
        }
        {
            const float* pv = (const float*)&pb;
            #pragma unroll
            for (int j = 0; j < 4; j++)
                *(uint2*)&B_s[bk][bq*4+j][0] = split_tf32(pv[j]);
        }
        if (c + 1 < 16) {
            int k0n = (c + 1) * 16;
            #pragma unroll
            for (int r = 0; r < 2; r++)
                pa[r] = *(const float4*)(W + (o0 + am + 64*r) * DIM_ + k0n + aq*4);
            pb = *(const float4*)(xb + (k0n + bk) * N_ + i0 + bq*4);
        }
        __syncthreads();
        #pragma unroll
        for (int ks = 0; ks < 2; ks++) {
            int k8 = ks * 8;
            uint2 Bf[4][2];
            #pragma unroll
            for (int nt = 0; nt < 4; nt++) {
                int cn = wn*32 + nt*8 + g;
                Bf[nt][0] = *(uint2*)&B_s[k8 + tig    ][cn][0];
                Bf[nt][1] = *(uint2*)&B_s[k8 + tig + 4][cn][0];
            }
            #pragma unroll
            for (int mt = 0; mt < 2; mt++) {
                int rm = wm*32 + mt*16 + g;
                unsigned A0 = A_s[k8 + tig    ][rm    ];
                unsigned A1 = A_s[k8 + tig    ][rm + 8];
                unsigned A2 = A_s[k8 + tig + 4][rm    ];
                unsigned A3 = A_s[k8 + tig + 4][rm + 8];
                #pragma unroll
                for (int nt = 0; nt < 4; nt++) {
                    mma8(acc[mt][nt], A0, A1, A2, A3, Bf[nt][0].x, Bf[nt][1].x);
                    mma8(acc[mt][nt], A0, A1, A2, A3, Bf[nt][0].y, Bf[nt][1].y);
                }
            }
        }
    }
    #pragma unroll
    for (int mt = 0; mt < 2; mt++) {
        int row = o0 + wm*32 + mt*16 + g;
        #pragma unroll
        for (int nt = 0; nt < 4; nt++) {
            int col = i0 + wn*32 + nt*8 + tig*2;
            *(float2*)(g_qkv + ((long)b*QKV_ + row    ) * N_ + col) =
                make_float2(acc[mt][nt][0], acc[mt][nt][1]);
            *(float2*)(g_qkv + ((long)b*QKV_ + row + 8) * N_ + col) =
                make_float2(acc[mt][nt][2], acc[mt][nt][3]);
        }
    }
}

// =================================================================
// Kernel K: softmax over n (1024) of each k row, in place.
// =================================================================
__global__ void __launch_bounds__(256) kK() {
    int row = blockIdx.x, b = blockIdx.y;
    float* p = g_qkv + ((long)b*QKV_ + HID_ + row) * N_;
    int t = threadIdx.x;
    __shared__ float red[8];
    float4 v = *(const float4*)(p + t*4);
    float m = fmaxf(fmaxf(v.x, v.y), fmaxf(v.z, v.w));
    #pragma unroll
    for (int o = 16; o; o >>= 1) m = fmaxf(m, __shfl_xor_sync(0xffffffffu, m, o));
    if ((t & 31) == 0) red[t >> 5] = m;
    __syncthreads();
    m = red[0];
    #pragma unroll
    for (int w = 1; w < 8; w++) m = fmaxf(m, red[w]);
    float e0 = __expf(v.x - m), e1 = __expf(v.y - m);
    float e2 = __expf(v.z - m), e3 = __expf(v.w - m);
    float s = e0 + e1 + e2 + e3;
    #pragma unroll
    for (int o = 16; o; o >>= 1) s += __shfl_xor_sync(0xffffffffu, s, o);
    __syncthreads();
    if ((t & 31) == 0) red[t >> 5] = s;
    __syncthreads();
    float tot = 0.f;
    #pragma unroll
    for (int w = 0; w < 8; w++) tot += red[w];
    float inv = 1.f / tot;
    *(float4*)(p + t*4) = make_float4(e0*inv, e1*inv, e2*inv, e3*inv);
}

// =================================================================
// Kernel KV (j-split x8, 4e x 4d tiles, bank-rotated):
//   KV[b][h][e][d] += sum_j k[e][j]*v[d][j]
// =================================================================
__global__ void __launch_bounds__(256) kKV() {
    int bh = blockIdx.x; int b = bh >> 2, h = bh & 3;
    int jbase = blockIdx.y * 128;
    __shared__ float ksm[32][33], vsm[32][33];
    int t = threadIdx.x;
    int jg = t & 3, dg = (t >> 2) & 7, eg = t >> 5;
    int e0 = eg * 4, d0 = dg * 4;
    float acc[4][4] = {};
    const float* kbase = g_qkv + ((long)b*QKV_ + HID_   + h*DH_) * N_;
    const float* vbase = g_qkv + ((long)b*QKV_ + 2*HID_ + h*DH_) * N_;
    for (int jc = 0; jc < 4; jc++) {
        int j0 = jbase + jc * 32;
        if (jc) __syncthreads();
        {
            int ee = t >> 3, j4 = t & 7;
            float4 kv = *(const float4*)(kbase + ee * N_ + j0 + j4*4);
            ksm[ee][j4*4+0] = kv.x; ksm[ee][j4*4+1] = kv.y;
            ksm[ee][j4*4+2] = kv.z; ksm[ee][j4*4+3] = kv.w;
            float4 vv = *(const float4*)(vbase + ee * N_ + j0 + j4*4);
            vsm[ee][j4*4+0] = vv.x; vsm[ee][j4*4+1] = vv.y;
            vsm[ee][j4*4+2] = vv.z; vsm[ee][j4*4+3] = vv.w;
        }
        __syncthreads();
        #pragma unroll
        for (int i = 0; i < 8; i++) {
            int jj = jg * 8 + ((i + dg) & 7);   // dg-rotation: conflict-free banks
            float kr[4], vr[4];
            #pragma unroll
            for (int u = 0; u < 4; u++) kr[u] = ksm[e0+u][jj];
            #pragma unroll
            for (int u = 0; u < 4; u++) vr[u] = vsm[d0+u][jj];
            #pragma unroll
            for (int u = 0; u < 4; u++)
                #pragma unroll
                for (int w2 = 0; w2 < 4; w2++)
                    acc[u][w2] += kr[u] * vr[w2];
        }
    }
    float* dst = g_KV + (long)bh * DH_ * DH_;
    #pragma unroll
    for (int u = 0; u < 4; u++)
        #pragma unroll
        for (int w2 = 0; w2 < 4; w2++)
            atomicAdd(dst + (e0+u)*DH_ + d0 + w2, acc[u][w2]);
}

// =================================================================
// Kernel Lin (fused q-softmax, d-split x2, float4 kv) -> g_lin
// =================================================================
__global__ void __launch_bounds__(128) kLin() {
    int it = blockIdx.x, hy = blockIdx.y, b = blockIdx.z;
    int h = hy >> 1, dh = (hy & 1) * 16;
    int i0 = it * 128, t = threadIdx.x;
    __shared__ float q_s[32][129];
    __shared__ float kv_s[32][20];   // stride 20: 16B-aligned rows
    for (int e = 0; e < 32; e++)
        q_s[e][t] = g_qkv[((long)b*QKV_ + h*DH_ + e) * N_ + i0 + t];
    #pragma unroll
    for (int r = 0; r < 4; r++) {
        int idx = t + r * 128;
        int e = idx >> 4, d = idx & 15;
        kv_s[e][d] = g_KV[(((long)(b*H_ + h))*DH_ + e) * DH_ + dh + d];
    }
    __syncthreads();
    float p[32];
    float m = -1e30f;
    #pragma unroll
    for (int e = 0; e < 32; e++) { p[e] = q_s[e][t]; m = fmaxf(m, p[e]); }
    float s = 0.f;
    #pragma unroll
    for (int e = 0; e < 32; e++) { p[e] = __expf(p[e] - m); s += p[e]; }
    float acc[16] = {};
    #pragma unroll 4
    for (int e = 0; e < 32; e++) {
        float pe = p[e];
        float4 k0 = *(float4*)&kv_s[e][0];
        float4 k1 = *(float4*)&kv_s[e][4];
        float4 k2 = *(float4*)&kv_s[e][8];
        float4 k3 = *(float4*)&kv_s[e][12];
        acc[0] += pe*k0.x; acc[1] += pe*k0.y; acc[2]  += pe*k0.z; acc[3]  += pe*k0.w;
        acc[4] += pe*k1.x; acc[5] += pe*k1.y; acc[6]  += pe*k1.z; acc[7]  += pe*k1.w;
        acc[8] += pe*k2.x; acc[9] += pe*k2.y; acc[10] += pe*k2.z; acc[11] += pe*k2.w;
        acc[12]+= pe*k3.x; acc[13]+= pe*k3.y; acc[14] += pe*k3.z; acc[15] += pe*k3.w;
    }
    float sc = SCALE_ / s;
    #pragma unroll
    for (int d = 0; d < 16; d++)
        g_lin[((long)b*HID_ + h*DH_ + dh + d) * N_ + i0 + t] = acc[d] * sc;
}

// =================================================================
// Kernel C (tf32 MMA, j-split x4): g_o2 += indicator-term (atomic)
// =================================================================
__global__ void __launch_bounds__(256) kC(const float* __restrict__ ind,
                                          const float* __restrict__ Wind) {
    int it = blockIdx.x, jchunk = blockIdx.y, b = blockIdx.z;
    int i0 = it * 64, jt0 = jchunk * 16, t = threadIdx.x;
    __shared__ unsigned qk_s[4][64][38];
    __shared__ unsigned v_s[16][136];

    int warp = t >> 5, lane = t & 31;
    int h  = warp >> 1;
    int n0 = (warp & 1) * 16;
    int g  = lane >> 2, tig = lane & 3;

    float w[4][5];
    #pragma unroll
    for (int hh = 0; hh < 4; hh++)
        #pragma unroll
        for (int c = 0; c < 5; c++) w[hh][c] = Wind[hh*INDC_ + c];

    int s_ii = t >> 2, s_j4 = (t & 3) * 4;
    int v_hd = t >> 2, v_jq = t & 3;
    const float* indb = ind + ((long)b * INDC_ << 20);
    const float* vbase = g_qkv + ((long)b*QKV_ + 2*HID_) * N_;

    float acc[4][2][4];
    #pragma unroll
    for (int mt = 0; mt < 4; mt++)
        #pragma unroll
        for (int nt = 0; nt < 2; nt++)
            #pragma unroll
            for (int z = 0; z < 4; z++) acc[mt][nt][z] = 0.f;

    float4 pind[5], pv[2];
    {
        int j0 = jt0 * 16;
        #pragma unroll
        for (int c = 0; c < 5; c++)
            pind[c] = *(const float4*)(indb + ((long)c << 20) + (long)(i0 + s_ii) * N_ + j0 + s_j4);
        #pragma unroll
        for (int r = 0; r < 2; r++)
            pv[r] = *(const float4*)(vbase + (long)(v_hd + 64*r) * N_ + j0 + v_jq*4);
    }

    for (int jt = 0; jt < 16; jt++) {
        if (jt) __syncthreads();
        #pragma unroll
        for (int r = 0; r < 2; r++) {
            const float* pf = (const float*)&pv[r];
            int hd = v_hd + 64*r;
            #pragma unroll
            for (int u = 0; u < 4; u++)
                v_s[v_jq*4+u][hd] = tf32u(pf[u]);
        }
        #pragma unroll
        for (int hh = 0; hh < 4; hh++) {
            float o0 = 0.f, o1 = 0.f, o2v = 0.f, o3 = 0.f;
            #pragma unroll
            for (int c = 0; c < 5; c++) {
                float wc = w[hh][c];
                o0 += wc * pind[c].x; o1 += wc * pind[c].y;
                o2v += wc * pind[c].z; o3 += wc * pind[c].w;
            }
            qk_s[hh][s_ii][s_j4+0] = tf32u(o0);
            qk_s[hh][s_ii][s_j4+1] = tf32u(o1);
            qk_s[hh][s_ii][s_j4+2] = tf32u(o2v);
            qk_s[hh][s_ii][s_j4+3] = tf32u(o3);
        }
        if (jt + 1 < 16) {
            int j0n = (jt0 + jt + 1) * 16;
            #pragma unroll
            for (int c = 0; c < 5; c++)
                pind[c] = *(const float4*)(indb + ((long)c << 20) + (long)(i0 + s_ii) * N_ + j0n + s_j4);
            #pragma unroll
            for (int r = 0; r < 2; r++)
                pv[r] = *(const float4*)(vbase + (long)(v_hd + 64*r) * N_ + j0n + v_jq*4);
        }
        __syncthreads();
        #pragma unroll
        for (int ks = 0; ks < 2; ks++) {
            int k0 = ks * 8;
            unsigned bfr[2][2];
            #pragma unroll
            for (int nt = 0; nt < 2; nt++) {
                int c = h*32 + n0 + nt*8 + g;
                bfr[nt][0] = v_s[k0 + tig][c];
                bfr[nt][1] = v_s[k0 + tig + 4][c];
            }
            #pragma unroll
            for (int mt = 0; mt < 4; mt++) {
                int r = mt*16 + g;
                unsigned a0 = qk_s[h][r    ][k0 + tig];
                unsigned a1 = qk_s[h][r + 8][k0 + tig];
                unsigned a2 = qk_s[h][r    ][k0 + tig + 4];
                unsigned a3 = qk_s[h][r + 8][k0 + tig + 4];
                mma8(acc[mt][0], a0, a1, a2, a3, bfr[0][0], bfr[0][1]);
                mma8(acc[mt][1], a0, a1, a2, a3, bfr[1][0], bfr[1][1]);
            }
        }
    }

    __syncthreads();
    float* out_s = (float*)&qk_s[0][0][0];
    #pragma unroll
    for (int mt = 0; mt < 4; mt++) {
        int r = mt*16 + g;
        #pragma unroll
        for (int nt = 0; nt < 2; nt++) {
            int c = h*32 + n0 + nt*8 + tig*2;
            out_s[ r     *129 + c    ] = acc[mt][nt][0];
            out_s[ r     *129 + c + 1] = acc[mt][nt][1];
            out_s[(r + 8)*129 + c    ] = acc[mt][nt][2];
            out_s[(r + 8)*129 + c + 1] = acc[mt][nt][3];
        }
    }
    __syncthreads();
    #pragma unroll
    for (int r2 = 0; r2 < 32; r2++) {
        int idx = t + r2*256, c = idx >> 6, ii = idx & 63;
        long p = ((long)b*HID_ + c) * N_ + i0 + ii;
        atomicAdd(&g_o2[p], out_s[ii*129 + c]);
    }
}

// =================================================================
// Kernel DLN (fused, 512 thr): y = W_out @ (o2+lin) + b_out, then LN
// =================================================================
__global__ void __launch_bounds__(512) kDLN(const float* __restrict__ W,
                                            const float* __restrict__ bias,
                                            const float* __restrict__ gam,
                                            float* __restrict__ out) {
    int it = blockIdx.x, b = blockIdx.y;
    int i0 = it * 32, t = threadIdx.x;
    __shared__ float W_s[8][260];
    __shared__ float X_s[8][36];
    __shared__ float red_s[32][65];
    __shared__ float red_q[32][65];
    __shared__ float mv[32][2];

    int og = t >> 3, ig = t & 7;
    float bo[4], ga[4];
    #pragma unroll
    for (int j = 0; j < 4; j++) { bo[j] = bias[og*4+j]; ga[j] = gam[og*4+j]; }

    int w_o = t >> 1, w_kq = t & 1;

    float acc[4][4] = {};
    for (int kc = 0; kc < 16; kc++) {
        int k0 = kc * 8;
        if (kc) __syncthreads();
        {
            float4 wv = *(const float4*)(W + (long)w_o * HID_ + k0 + w_kq*4);
            const float* wf = (const float*)&wv;
            #pragma unroll
            for (int j = 0; j < 4; j++) W_s[w_kq*4+j][w_o] = wf[j];
        }
        if (t < 256) {
            long p = ((long)b*HID_ + k0 + (t>>5)) * N_ + i0 + (t & 31);
            X_s[t>>5][t&31] = g_o2[p] + g_lin[p];
        }
        __syncthreads();
        #pragma unroll
        for (int k = 0; k < 8; k++) {
            float4 w4 = *(float4*)&W_s[k][og*4];
            float4 x4 = *(float4*)&X_s[k][ig*4];
            const float* wf = (const float*)&w4;
            const float* xf = (const float*)&x4;
            #pragma unroll
            for (int j = 0; j < 4; j++)
                #pragma unroll
                for (int ii = 0; ii < 4; ii++)
                    acc[j][ii] += wf[j] * xf[ii];
        }
    }
    #pragma unroll
    for (int j = 0; j < 4; j++)
        #pragma unroll
        for (int ii = 0; ii < 4; ii++) acc[j][ii] += bo[j];

    __syncthreads();
    #pragma unroll
    for (int ii = 0; ii < 4; ii++) {
        float s = 0.f, q = 0.f;
        #pragma unroll
        for (int j = 0; j < 4; j++) { s += acc[j][ii]; q += acc[j][ii]*acc[j][ii]; }
        red_s[ig*4+ii][og] = s;
        red_q[ig*4+ii][og] = q;
    }
    __syncthreads();
    if (t < 32) {
        float s = 0.f, q = 0.f;
        #pragma unroll
        for (int o = 0; o < 64; o++) { s += red_s[t][o]; q += red_q[t][o]; }
        float mean = s * (1.f / DIM_);
        float var  = q * (1.f / DIM_) - mean * mean;
        mv[t][0] = mean;
        mv[t][1] = rsqrtf(var + EPS_);
    }
    __syncthreads();
    float mloc[4], rloc[4];
    #pragma unroll
    for (int ii = 0; ii < 4; ii++) { mloc[ii] = mv[ig*4+ii][0]; rloc[ii] = mv[ig*4+ii][1]; }
    #pragma unroll
    for (int j = 0; j < 4; j++) {
        float4 o4;
        float* of = (float*)&o4;
        #pragma unroll
        for (int ii = 0; ii < 4; ii++)
            of[ii] = (acc[j][ii] - mloc[ii]) * rloc[ii] * ga[j];
        *(float4*)(out + ((long)b*DIM_ + og*4 + j) * N_ + i0 + ig*4) = o4;
    }
}

// =================================================================
extern "C" void kernel_launch(void* const* d_in, const int* in_sizes, int n_in,
                              void* d_out, int out_size) {
    const float* x     = (const float*)d_in[0];
    const float* ind   = (const float*)d_in[1];
    const float* Wqkv  = (const float*)d_in[2];
    const float* Wind  = (const float*)d_in[3];
    const float* Wout  = (const float*)d_in[4];
    const float* bout  = (const float*)d_in[5];
    const float* gam   = (const float*)d_in[6];
    float* out = (float*)d_out;

    static cudaStream_t s1 = nullptr;
    static cudaEvent_t evStart = nullptr, evA = nullptr, evC = nullptr;
    if (!s1) {
        cudaStreamCreateWithFlags(&s1, cudaStreamNonBlocking);
        cudaEventCreateWithFlags(&evStart, cudaEventDisableTiming);
        cudaEventCreateWithFlags(&evA, cudaEventDisableTiming);
        cudaEventCreateWithFlags(&evC, cudaEventDisableTiming);
    }

    void* kvptr = nullptr; cudaGetSymbolAddress(&kvptr, g_KV);
    void* o2ptr = nullptr; cudaGetSymbolAddress(&o2ptr, g_o2);

    cudaEventRecord(evStart, 0);
    cudaStreamWaitEvent(s1, evStart, 0);

    cudaMemsetAsync(o2ptr, 0, sizeof(float)*B_*HID_*N_, s1);

    kA<<<dim3(16, 3, B_), 256>>>(Wqkv, x);
    cudaEventRecord(evA, 0);

    cudaStreamWaitEvent(s1, evA, 0);
    kC<<<dim3(16, 4, B_), 256, 0, s1>>>(ind, Wind);
    cudaEventRecord(evC, s1);

    cudaMemsetAsync(kvptr, 0, sizeof(float)*B_*H_*DH_*DH_, 0);
    kK  <<<dim3(HID_, B_), 256>>>();
    kKV <<<dim3(B_*H_, 8), 256>>>();
    kLin<<<dim3(8, 8, B_), 128>>>();

    cudaStreamWaitEvent(0, evC, 0);
    kDLN<<<dim3(32, B_), 512>>>(Wout, bout, gam, out);
}